// round 11
// baseline (speedup 1.0000x reference)
#include <cuda_runtime.h>
#include <cuda_bf16.h>
#include <cuda_fp16.h>
#include <cstdint>
#include <math.h>

// Problem constants
#define Nn    20000
#define Mpad  20096            // 157 * 128
#define Ee    320000
#define EA    (Ee + Nn)
#define INF_  128
#define Hh    6
#define Cc    64
#define HCc   384
#define NGg   64
#define NCc   16

// weight-prep element offsets in concatenated [N x K] K-major bf16 buffers
#define W0OFF 0                // layer0: 1152 x 128
#define W1OFF 147456           // layer1: 768 x 384
#define W2OFF 442368           // layer2: 256 x 384 (rows 192..255 zero pad)
#define WTOT  540672
#define B0OFF 0
#define B1OFF 1152
#define B2OFF 1920
#define BTOT  2176

// ---------------- device scratch ----------------
__device__ __align__(16) __nv_bfloat16 g_ah[(size_t)Mpad * HCc];
__device__ __align__(16) __nv_bfloat16 g_al[(size_t)Mpad * HCc];
__device__ __align__(16) __half        g_hf[(size_t)Mpad * HCc];   // fp16 xl copy
__device__ __align__(16) __nv_bfloat16 g_wh[WTOT];
__device__ __align__(16) __nv_bfloat16 g_wl[WTOT];
__device__ float g_biascat[BTOT];
__device__ float g_big[(size_t)Mpad * 1152];
__device__ int   g_deg[Nn + 1];
__device__ int   g_indptr[Nn + 1];
__device__ int   g_cursor[Nn];
__device__ int   g_esrc[EA + 8];               // src node per CSR slot (+8 pad)
__device__ float g_pool[NGg * Cc];

// ---------------- PTX helpers (plain sm_80+ features only) ----------------
__device__ __forceinline__ uint32_t smem_u32(const void* p) {
    uint32_t a;
    asm("{ .reg .u64 t; cvta.to.shared.u64 t, %1; cvt.u32.u64 %0, t; }" : "=r"(a) : "l"(p));
    return a;
}
#define CPASY16(dst, src) asm volatile("cp.async.cg.shared.global [%0], [%1], 16;" :: "r"(dst), "l"(src))
#define CPASY_COMMIT()    asm volatile("cp.async.commit_group;" ::: "memory")
#define CPASY_WAIT1()     asm volatile("cp.async.wait_group 1;" ::: "memory")
#define CPASY_WAIT0()     asm volatile("cp.async.wait_group 0;" ::: "memory")

__device__ __forceinline__ void ldm_x4(uint32_t* r, uint32_t addr) {
    asm volatile("ldmatrix.sync.aligned.m8n8.x4.shared.b16 {%0,%1,%2,%3}, [%4];"
        : "=r"(r[0]), "=r"(r[1]), "=r"(r[2]), "=r"(r[3]) : "r"(addr));
}
__device__ __forceinline__ void mma_bf16(float* d, const uint32_t* a,
                                         uint32_t b0, uint32_t b1) {
    asm volatile("mma.sync.aligned.m16n8k16.row.col.f32.bf16.bf16.f32 "
        "{%0,%1,%2,%3}, {%4,%5,%6,%7}, {%8,%9}, {%0,%1,%2,%3};"
        : "+f"(d[0]), "+f"(d[1]), "+f"(d[2]), "+f"(d[3])
        : "r"(a[0]), "r"(a[1]), "r"(a[2]), "r"(a[3]), "r"(b0), "r"(b1));
}

// ---------------- consolidated prep: clears + weight split + bias concat ----------------
__global__ void prep_all(
    const float* __restrict__ inpw,
    const float* __restrict__ l0wl, const float* __restrict__ l0wr,
    const float* __restrict__ l1wl, const float* __restrict__ l1wr,
    const float* __restrict__ l2wl, const float* __restrict__ l2wr,
    const float* __restrict__ resw,
    const float* __restrict__ inpb,
    const float* __restrict__ l0bl, const float* __restrict__ l0br,
    const float* __restrict__ l1bl, const float* __restrict__ l1br,
    const float* __restrict__ l2bl, const float* __restrict__ l2br)
{
    int idx = blockIdx.x * blockDim.x + threadIdx.x;
    if (idx < 8) g_esrc[EA + idx] = 0;   // prefetch pad
    if (idx < WTOT) {
        float v;
        if (idx < W1OFF) {                       // W0: 1152 x 128
            int ng = idx >> 7, k = idx & 127;
            int sub = ng / 384, nl = ng - sub * 384;
            const float* w = (sub == 0) ? inpw : (sub == 1) ? l0wl : l0wr;
            v = w[k * 384 + nl];
        } else if (idx < W2OFF) {                // W1: 768 x 384
            int rem = idx - W1OFF;
            int ng = rem / 384, k = rem - ng * 384;
            const float* w = (ng < 384) ? l1wl : l1wr;
            int nl = (ng < 384) ? ng : ng - 384;
            v = w[k * 384 + nl];
        } else {                                 // W2: 256 x 384 (pad >=192)
            int rem = idx - W2OFF;
            int ng = rem / 384, k = rem - ng * 384;
            if      (ng < 64)  v = l2wl[k * 64 + ng];
            else if (ng < 128) v = l2wr[k * 64 + ng - 64];
            else if (ng < 192) v = resw[k * 64 + ng - 128];
            else               v = 0.f;
        }
        __nv_bfloat16 hi = __float2bfloat16(v);
        g_wh[idx] = hi;
        g_wl[idx] = __float2bfloat16(v - __bfloat162float(hi));
        return;
    }
    int r = idx - WTOT;
    if (r < BTOT) {
        float v = 0.f;
        if      (r < 384)  v = inpb[r];
        else if (r < 768)  v = l0bl[r - 384];
        else if (r < 1152) v = l0br[r - 768];
        else if (r < 1536) v = l1bl[r - 1152];
        else if (r < 1920) v = l1br[r - 1536];
        else if (r < 1984) v = l2bl[r - 1920];
        else if (r < 2048) v = l2br[r - 1984];
        g_biascat[r] = v;
        return;
    }
    r -= BTOT;
    if (r < Nn) { g_deg[r] = 0; return; }
    r -= Nn;
    if (r < NGg * Cc) g_pool[r] = 0.f;
}
#define PREP_TOT (WTOT + BTOT + Nn + NGg * Cc)

// ---------------- CSR build ----------------
__global__ void csr_count(const int* __restrict__ ei) {
    int e = blockIdx.x * blockDim.x + threadIdx.x;
    if (e >= EA) return;
    int d = (e < Ee) ? ei[Ee + e] : (e - Ee);
    atomicAdd(&g_deg[d], 1);
}

__global__ void csr_scan() {
    __shared__ int part[1024];
    const int per = (Nn + 1023) / 1024;
    int t = threadIdx.x;
    int s = 0;
    #pragma unroll
    for (int k = 0; k < per; ++k) { int i = t * per + k; if (i < Nn) s += g_deg[i]; }
    part[t] = s;
    __syncthreads();
    for (int off = 1; off < 1024; off <<= 1) {
        int v = (t >= off) ? part[t - off] : 0;
        __syncthreads();
        part[t] += v;
        __syncthreads();
    }
    int run = part[t] - s;
    #pragma unroll
    for (int k = 0; k < per; ++k) {
        int i = t * per + k;
        if (i < Nn) { g_indptr[i] = run; g_cursor[i] = run; run += g_deg[i]; }
    }
    if (t == 0) g_indptr[Nn] = EA;
}

__global__ void csr_scatter(const int* __restrict__ ei) {
    int e = blockIdx.x * blockDim.x + threadIdx.x;
    if (e >= EA) return;
    int s, d;
    if (e < Ee) { s = ei[e]; d = ei[Ee + e]; }
    else        { s = d = e - Ee; }
    int pos = atomicAdd(&g_cursor[d], 1);
    g_esrc[pos] = s;
}

// fp32 -> (hi, lo) bf16 split (layer-0 input only)
__global__ void conv_hilo(const float* __restrict__ src, int n4) {
    int i = blockIdx.x * blockDim.x + threadIdx.x;
    if (i >= n4) return;
    float4 v = reinterpret_cast<const float4*>(src)[i];
    __nv_bfloat16 h0 = __float2bfloat16(v.x), h1 = __float2bfloat16(v.y);
    __nv_bfloat16 h2 = __float2bfloat16(v.z), h3 = __float2bfloat16(v.w);
    g_ah[i * 4 + 0] = h0; g_ah[i * 4 + 1] = h1;
    g_ah[i * 4 + 2] = h2; g_ah[i * 4 + 3] = h3;
    g_al[i * 4 + 0] = __float2bfloat16(v.x - __bfloat162float(h0));
    g_al[i * 4 + 1] = __float2bfloat16(v.y - __bfloat162float(h1));
    g_al[i * 4 + 2] = __float2bfloat16(v.z - __bfloat162float(h2));
    g_al[i * 4 + 3] = __float2bfloat16(v.w - __bfloat162float(h3));
}

// ---------------- HMMA split-bf16 GEMM, 4-buffer single-K-pass ----------------
#define PADK 40
#define TILEB (128 * PADK * 2)     // 10240 bytes per tile
#define STAGEB (4 * TILEB)         // 40960 bytes per stage
#define SMEM_MM (2 * STAGEB)       // 81920

__global__ __launch_bounds__(256, 2) void mm_mma(
    const __nv_bfloat16* __restrict__ Ah, const __nv_bfloat16* __restrict__ Al,
    const __nv_bfloat16* __restrict__ Bh, const __nv_bfloat16* __restrict__ Bl,
    const float* __restrict__ bias, float* __restrict__ out,
    __half* __restrict__ hout, int hld, int hcol0, int hcolw,
    int K, int ldout)
{
    extern __shared__ __align__(16) char dsm[];
    uint32_t sbase = smem_u32(dsm);
    int tid = threadIdx.x, wid = tid >> 5, lane = tid & 31;
    int m0 = blockIdx.y * 128, n0 = blockIdx.x * 128;
    int warp_m = wid & 3, warp_n = wid >> 2;
    int nk = K >> 5;

    auto load_chunk = [&](int stage, int k0) {
        uint32_t dst0 = sbase + stage * STAGEB;
        #pragma unroll
        for (int it = 0; it < 8; ++it) {
            int idx = tid + it * 256;
            int buf = idx >> 9;
            int w   = idx & 511;
            int r   = w >> 2, q = w & 3;
            const __nv_bfloat16* src;
            if      (buf == 0) src = Ah + (size_t)(m0 + r) * K + k0 + q * 8;
            else if (buf == 1) src = Al + (size_t)(m0 + r) * K + k0 + q * 8;
            else if (buf == 2) src = Bh + (size_t)(n0 + r) * K + k0 + q * 8;
            else               src = Bl + (size_t)(n0 + r) * K + k0 + q * 8;
            CPASY16(dst0 + buf * TILEB + (r * PADK + q * 8) * 2, src);
        }
        CPASY_COMMIT();
    };

    load_chunk(0, 0);

    float acc[2][8][4];
    #pragma unroll
    for (int mi = 0; mi < 2; ++mi)
        #pragma unroll
        for (int nt = 0; nt < 8; ++nt)
            #pragma unroll
            for (int q = 0; q < 4; ++q) acc[mi][nt][q] = 0.f;

    int gA = lane >> 3, lrA = lane & 7;

    for (int c = 0; c < nk; ++c) {
        int s = c & 1;
        if (c + 1 < nk) { load_chunk(s ^ 1, (c + 1) << 5); CPASY_WAIT1(); }
        else            { CPASY_WAIT0(); }
        __syncthreads();

        uint32_t st = sbase + s * STAGEB;
        uint32_t aH = st + (warp_m * 32) * PADK * 2;
        uint32_t aL = st + TILEB + (warp_m * 32) * PADK * 2;
        uint32_t bH = st + 2 * TILEB + (warp_n * 64) * PADK * 2;
        uint32_t bL = st + 3 * TILEB + (warp_n * 64) * PADK * 2;

        #pragma unroll
        for (int kk = 0; kk < 32; kk += 16) {
            uint32_t afrH[2][4], afrL[2][4];
            #pragma unroll
            for (int mi = 0; mi < 2; ++mi) {
                int row = mi * 16 + ((gA & 1) << 3) + lrA;
                int col = ((gA >> 1) << 3) + kk;
                ldm_x4(afrH[mi], aH + (row * PADK + col) * 2);
                ldm_x4(afrL[mi], aL + (row * PADK + col) * 2);
            }
            uint32_t bfr[4][4];
            #pragma unroll
            for (int nb = 0; nb < 4; ++nb) {
                int n = nb * 16 + ((gA >> 1) << 3) + lrA;
                int col = ((gA & 1) << 3) + kk;
                ldm_x4(bfr[nb], bH + (n * PADK + col) * 2);
            }
            #pragma unroll
            for (int mi = 0; mi < 2; ++mi)
                #pragma unroll
                for (int nt = 0; nt < 8; ++nt) {
                    mma_bf16(acc[mi][nt], afrH[mi],
                             bfr[nt >> 1][(nt & 1) * 2], bfr[nt >> 1][(nt & 1) * 2 + 1]);
                    mma_bf16(acc[mi][nt], afrL[mi],
                             bfr[nt >> 1][(nt & 1) * 2], bfr[nt >> 1][(nt & 1) * 2 + 1]);
                }
            #pragma unroll
            for (int nb = 0; nb < 4; ++nb) {
                int n = nb * 16 + ((gA >> 1) << 3) + lrA;
                int col = ((gA & 1) << 3) + kk;
                ldm_x4(bfr[nb], bL + (n * PADK + col) * 2);
            }
            #pragma unroll
            for (int mi = 0; mi < 2; ++mi)
                #pragma unroll
                for (int nt = 0; nt < 8; ++nt)
                    mma_bf16(acc[mi][nt], afrH[mi],
                             bfr[nt >> 1][(nt & 1) * 2], bfr[nt >> 1][(nt & 1) * 2 + 1]);
        }
        __syncthreads();
    }

    int rl = lane >> 2, cl = (lane & 3) * 2;
    #pragma unroll
    for (int mi = 0; mi < 2; ++mi) {
        int r0 = m0 + warp_m * 32 + mi * 16 + rl;
        #pragma unroll
        for (int nt = 0; nt < 8; ++nt) {
            int cb = n0 + warp_n * 64 + nt * 8 + cl;
            float b0 = bias[cb], b1 = bias[cb + 1];
            bool inh = (unsigned)(cb - hcol0) < (unsigned)hcolw;
            int hc = cb - hcol0;
            if (r0 < Nn) {
                float v0 = acc[mi][nt][0] + b0, v1 = acc[mi][nt][1] + b1;
                if (inh)
                    *reinterpret_cast<__half2*>(&hout[(size_t)r0 * hld + hc]) = __floats2half2_rn(v0, v1);
                else {
                    float2 v = { v0, v1 };
                    *reinterpret_cast<float2*>(&out[(size_t)r0 * ldout + cb]) = v;
                }
            }
            if (r0 + 8 < Nn) {
                float v0 = acc[mi][nt][2] + b0, v1 = acc[mi][nt][3] + b1;
                if (inh)
                    *reinterpret_cast<__half2*>(&hout[(size_t)(r0 + 8) * hld + hc]) = __floats2half2_rn(v0, v1);
                else {
                    float2 v = { v0, v1 };
                    *reinterpret_cast<float2*>(&out[(size_t)(r0 + 8) * ldout + cb]) = v;
                }
            }
        }
    }
}

// ---------------- fused GATv2: 4 edge-groups x 8 lanes, half2 logit math ----------------
// Warp per (node, head). Lane group grp (0..3) handles edges beg+grp, beg+grp+4, ...
// Lane covers 8 consecutive channels (one ld.128 per edge). Intra-group shuffles
// use the GROUP mask (groups have divergent trip counts); cross-group combine
// happens after __syncwarp reconvergence. Plain-exp softmax (logits bounded).
__global__ void gat_fused(
    const __half* __restrict__ xh, int xld8,
    const float* __restrict__ big, int ld, int offR,
    const float* __restrict__ att, const float* __restrict__ bias,
    const float* __restrict__ resf, int ldresf,
    const __nv_bfloat16* __restrict__ resh, const __nv_bfloat16* __restrict__ resl, int ldresb,
    float* __restrict__ outf, int ldoutf,
    __nv_bfloat16* __restrict__ outh, __nv_bfloat16* __restrict__ outl,
    const int* __restrict__ pool_batch, int H, int npb)
{
    int wid = threadIdx.x >> 5;
    int lane = threadIdx.x & 31;
    int node = blockIdx.x * npb + wid / H;
    int head = wid - (wid / H) * H;
    if (node >= Nn) return;
    int grp = lane >> 3, gl = lane & 7;
    unsigned gmask = 0xFFu << (grp * 8);      // this group's 8 convergent lanes
    int beg = g_indptr[node], end = g_indptr[node + 1];
    int c0 = head * 64 + gl * 8;

    float4 a0 = *reinterpret_cast<const float4*>(att + c0);
    float4 a1 = *reinterpret_cast<const float4*>(att + c0 + 4);
    __half2 ah[4] = { __floats2half2_rn(a0.x, a0.y), __floats2half2_rn(a0.z, a0.w),
                      __floats2half2_rn(a1.x, a1.y), __floats2half2_rn(a1.z, a1.w) };
    const float* xrp = big + (size_t)node * ld + offR + c0;
    float4 r0f = *reinterpret_cast<const float4*>(xrp);
    float4 r1f = *reinterpret_cast<const float4*>(xrp + 4);
    __half2 xrh[4] = { __floats2half2_rn(r0f.x, r0f.y), __floats2half2_rn(r0f.z, r0f.w),
                       __floats2half2_rn(r1f.x, r1f.y), __floats2half2_rn(r1f.z, r1f.w) };
    const __half2 p2 = __floats2half2_rn(0.2f, 0.2f);

    const uint4* xb = reinterpret_cast<const uint4*>(xh);
    int coff = head * 8 + gl;

    float ssum = 0.f;
    float acc[8] = {};
    int j0 = beg + grp;
    uint4 hv_next = xb[(size_t)g_esrc[j0] * xld8 + coff];   // esrc padded -> safe

    for (int j = j0; j < end; j += 4) {
        uint4 hv = hv_next;
        hv_next = xb[(size_t)g_esrc[j + 4] * xld8 + coff];
        const __half2* xvh = reinterpret_cast<const __half2*>(&hv);
        __half2 dot = __floats2half2_rn(0.f, 0.f);
        #pragma unroll
        for (int k = 0; k < 4; ++k) {
            __half2 t = __hadd2(xvh[k], xrh[k]);
            __half2 tl = __hmax2(t, __hmul2(t, p2));     // leaky_relu(0.2)
            dot = __hfma2(ah[k], tl, dot);
        }
        float p = __low2float(dot) + __high2float(dot);
        p += __shfl_xor_sync(gmask, p, 1);
        p += __shfl_xor_sync(gmask, p, 2);
        p += __shfl_xor_sync(gmask, p, 4);
        float w = __expf(p);
        ssum += w;
        #pragma unroll
        for (int k = 0; k < 4; ++k) {
            float2 xv = __half22float2(xvh[k]);
            acc[2 * k]     = fmaf(w, xv.x, acc[2 * k]);
            acc[2 * k + 1] = fmaf(w, xv.y, acc[2 * k + 1]);
        }
    }
    // reconverge, then combine the 4 edge-groups
    __syncwarp();
    #pragma unroll
    for (int o = 8; o <= 16; o <<= 1) {
        ssum += __shfl_xor_sync(0xffffffffu, ssum, o);
        #pragma unroll
        for (int k = 0; k < 8; ++k)
            acc[k] += __shfl_xor_sync(0xffffffffu, acc[k], o);
    }
    if (grp != 0) return;

    float inv = 1.f / (ssum + 1e-16f);
    float4 b0 = *reinterpret_cast<const float4*>(bias + c0);
    float4 b1 = *reinterpret_cast<const float4*>(bias + c0 + 4);
    float bb[8] = { b0.x, b0.y, b0.z, b0.w, b1.x, b1.y, b1.z, b1.w };
    float v[8];
    #pragma unroll
    for (int k = 0; k < 8; ++k) {
        float t = acc[k] * inv + bb[k];
        v[k] = (t > 0.f) ? t : (__expf(t) - 1.f);        // ELU
    }
    if (resf) {
        const float* rp = resf + (size_t)node * ldresf + c0;
        float4 q0 = *reinterpret_cast<const float4*>(rp);
        float4 q1 = *reinterpret_cast<const float4*>(rp + 4);
        v[0] += q0.x; v[1] += q0.y; v[2] += q0.z; v[3] += q0.w;
        v[4] += q1.x; v[5] += q1.y; v[6] += q1.z; v[7] += q1.w;
    } else {
        uint4 rhu = *reinterpret_cast<const uint4*>(resh + (size_t)node * ldresb + c0);
        uint4 rlu = *reinterpret_cast<const uint4*>(resl + (size_t)node * ldresb + c0);
        const __nv_bfloat162* rh2 = reinterpret_cast<const __nv_bfloat162*>(&rhu);
        const __nv_bfloat162* rl2 = reinterpret_cast<const __nv_bfloat162*>(&rlu);
        #pragma unroll
        for (int k = 0; k < 4; ++k) {
            float2 fh = __bfloat1622float2(rh2[k]);
            float2 fl = __bfloat1622float2(rl2[k]);
            v[2 * k]     += fh.x + fl.x;
            v[2 * k + 1] += fh.y + fl.y;
        }
    }
    if (outf) {
        float* op = outf + (size_t)node * ldoutf + c0;
        *reinterpret_cast<float4*>(op)     = make_float4(v[0], v[1], v[2], v[3]);
        *reinterpret_cast<float4*>(op + 4) = make_float4(v[4], v[5], v[6], v[7]);
    }
    if (outh) {
        __nv_bfloat162 hv2[4], lv2[4];
        #pragma unroll
        for (int k = 0; k < 4; ++k) {
            __nv_bfloat16 h0 = __float2bfloat16(v[2 * k]), h1 = __float2bfloat16(v[2 * k + 1]);
            hv2[k].x = h0; hv2[k].y = h1;
            lv2[k].x = __float2bfloat16(v[2 * k] - __bfloat162float(h0));
            lv2[k].y = __float2bfloat16(v[2 * k + 1] - __bfloat162float(h1));
        }
        *reinterpret_cast<uint4*>(outh + (size_t)node * HCc + c0) = *reinterpret_cast<uint4*>(hv2);
        *reinterpret_cast<uint4*>(outl + (size_t)node * HCc + c0) = *reinterpret_cast<uint4*>(lv2);
    }
    if (pool_batch) {                              // fused graph pooling (layer 2, head 0)
        int g = pool_batch[node];
        #pragma unroll
        for (int k = 0; k < 8; ++k)
            atomicAdd(&g_pool[g * Cc + c0 + k], v[k]);
    }
}

// ---------------- dense head ----------------
__global__ __launch_bounds__(1024) void dense_head(
    const float* __restrict__ d1w, const float* __restrict__ d1b,
    const float* __restrict__ bng, const float* __restrict__ bnb,
    const float* __restrict__ bnm, const float* __restrict__ bnv,
    const float* __restrict__ d2w, const float* __restrict__ d2b,
    float* __restrict__ z)
{
    __shared__ float sp[NGg * Cc];
    __shared__ float t1[NGg * Cc];
    int tid = threadIdx.x;
    for (int idx = tid; idx < NGg * Cc; idx += 1024) sp[idx] = g_pool[idx];
    __syncthreads();
    for (int idx = tid; idx < NGg * Cc; idx += 1024) {
        int r = idx >> 6, c = idx & 63;
        float s = d1b[c];
        #pragma unroll
        for (int k = 0; k < 64; ++k) s = fmaf(sp[r * 64 + k], d1w[k * 64 + c], s);
        s = (s - bnm[c]) * rsqrtf(bnv[c] + 1e-5f) * bng[c] + bnb[c];
        t1[idx] = (s > 0.f) ? s : 0.f;
    }
    __syncthreads();
    for (int idx = tid; idx < NGg * NCc; idx += 1024) {
        int r = idx >> 4, c = idx & 15;
        float s = d2b[c];
        #pragma unroll
        for (int k = 0; k < 64; ++k) s = fmaf(t1[r * 64 + k], d2w[k * 16 + c], s);
        z[idx] = s;
    }
}

// ---------------- host launcher ----------------
extern "C" void kernel_launch(void* const* d_in, const int* in_sizes, int n_in,
                              void* d_out, int out_size)
{
    const float* x      = (const float*)d_in[0];
    const int*   ei     = (const int*)  d_in[1];
    const int*   batch  = (const int*)  d_in[2];
    const float* inp_w  = (const float*)d_in[3];
    const float* inp_b  = (const float*)d_in[4];
    const float* l0_wl  = (const float*)d_in[5];
    const float* l0_bl  = (const float*)d_in[6];
    const float* l0_wr  = (const float*)d_in[7];
    const float* l0_br  = (const float*)d_in[8];
    const float* l0_att = (const float*)d_in[9];
    const float* l0_bias= (const float*)d_in[10];
    const float* l1_wl  = (const float*)d_in[11];
    const float* l1_bl  = (const float*)d_in[12];
    const float* l1_wr  = (const float*)d_in[13];
    const float* l1_br  = (const float*)d_in[14];
    const float* l1_att = (const float*)d_in[15];
    const float* l1_bias= (const float*)d_in[16];
    const float* l2_wl  = (const float*)d_in[17];
    const float* l2_bl  = (const float*)d_in[18];
    const float* l2_wr  = (const float*)d_in[19];
    const float* l2_br  = (const float*)d_in[20];
    const float* l2_att = (const float*)d_in[21];
    const float* l2_bias= (const float*)d_in[22];
    const float* res_w  = (const float*)d_in[23];
    const float* d1_w   = (const float*)d_in[24];
    const float* d1_b   = (const float*)d_in[25];
    const float* bn_g   = (const float*)d_in[26];
    const float* bn_b   = (const float*)d_in[27];
    const float* bn_m   = (const float*)d_in[28];
    const float* bn_v   = (const float*)d_in[29];
    const float* d2_w   = (const float*)d_in[30];
    const float* d2_b   = (const float*)d_in[31];
    float* out = (float*)d_out;

    float *p_big, *p_bias;
    __nv_bfloat16 *p_ah, *p_al, *p_wh, *p_wl;
    __half *p_hf;
    cudaGetSymbolAddress((void**)&p_big,  g_big);
    cudaGetSymbolAddress((void**)&p_ah,   g_ah);
    cudaGetSymbolAddress((void**)&p_al,   g_al);
    cudaGetSymbolAddress((void**)&p_wh,   g_wh);
    cudaGetSymbolAddress((void**)&p_wl,   g_wl);
    cudaGetSymbolAddress((void**)&p_hf,   g_hf);
    cudaGetSymbolAddress((void**)&p_bias, g_biascat);

    cudaFuncSetAttribute(mm_mma, cudaFuncAttributeMaxDynamicSharedMemorySize, SMEM_MM);

    // ---- consolidated prep + CSR build ----
    prep_all<<<(PREP_TOT + 255) / 256, 256>>>(
        inp_w, l0_wl, l0_wr, l1_wl, l1_wr, l2_wl, l2_wr, res_w,
        inp_b, l0_bl, l0_br, l1_bl, l1_br, l2_bl, l2_br);
    csr_count<<<(EA + 255) / 256, 256>>>(ei);
    csr_scan<<<1, 1024>>>();
    csr_scatter<<<(EA + 255) / 256, 256>>>(ei);

    const int MB = 157;  // ceil(20000/128)

    // ---- layer 0: fused GEMM [x_res | xl | xr], K=128, Ntot=1152 ----
    conv_hilo<<<(Nn * 128 / 4 + 255) / 256, 256>>>(x, Nn * 128 / 4);
    mm_mma<<<dim3(9, MB), 256, SMEM_MM>>>(p_ah, p_al, p_wh + W0OFF, p_wl + W0OFF,
                                          p_bias + B0OFF, p_big,
                                          p_hf, 384, 384, 384, 128, 1152);
    gat_fused<<<Nn, 32 * Hh>>>(p_hf, 48, p_big, 1152, 768, l0_att, l0_bias,
                               p_big, 1152, nullptr, nullptr, 0,
                               nullptr, 0, p_ah, p_al, nullptr, Hh, 1);   // h0 -> ah/al

    // ---- layer 1: fused GEMM [xl | xr], K=384, Ntot=768 ----
    mm_mma<<<dim3(6, MB), 256, SMEM_MM>>>(p_ah, p_al, p_wh + W1OFF, p_wl + W1OFF,
                                          p_bias + B1OFF, p_big,
                                          p_hf, 384, 0, 384, 384, 768);
    gat_fused<<<Nn, 32 * Hh>>>(p_hf, 48, p_big, 768, 384, l1_att, l1_bias,
                               nullptr, 0, p_ah, p_al, HCc,
                               nullptr, 0, p_ah, p_al, nullptr, Hh, 1);   // res=h0, h1 -> ah/al

    // ---- layer 2: fused GEMM [xl | xr | res_proj | pad], K=384, Ntot=256 ----
    mm_mma<<<dim3(2, MB), 256, SMEM_MM>>>(p_ah, p_al, p_wh + W2OFF, p_wl + W2OFF,
                                          p_bias + B2OFF, p_big,
                                          p_hf, 64, 0, 64, 384, 256);
    gat_fused<<<(Nn + 7) / 8, 256>>>(p_hf, 8, p_big, 256, 64, l2_att, l2_bias,
                                     p_big + 128, 256, nullptr, nullptr, 0,
                                     out, 64, nullptr, nullptr, batch, 1, 8);  // h -> d_out, fused pool

    // ---- dense head ----
    dense_head<<<1, 1024>>>(d1_w, d1_b, bn_g, bn_b, bn_m, bn_v, d2_w, d2_b,
                            out + (size_t)Nn * Cc);
}

// round 12
// speedup vs baseline: 1.0489x; 1.0489x over previous
#include <cuda_runtime.h>
#include <cuda_bf16.h>
#include <cuda_fp16.h>
#include <cstdint>
#include <math.h>

// Problem constants
#define Nn    20000
#define Mpad  20096            // 157 * 128
#define Ee    320000
#define EA    (Ee + Nn)
#define INF_  128
#define Hh    6
#define Cc    64
#define HCc   384
#define NGg   64
#define NCc   16

// weight-prep element offsets in concatenated [N x K] K-major bf16 buffers
#define W0OFF 0                // layer0: 1152 x 128
#define W1OFF 147456           // layer1: 768 x 384
#define W2OFF 442368           // layer2: 256 x 384 (rows 192..255 zero pad)
#define WTOT  540672
#define B0OFF 0
#define B1OFF 1152
#define B2OFF 1920
#define BTOT  2176

// ---------------- device scratch ----------------
__device__ __align__(16) __nv_bfloat16 g_ah[(size_t)Mpad * HCc];
__device__ __align__(16) __nv_bfloat16 g_al[(size_t)Mpad * HCc];
__device__ __align__(16) __half        g_hf[(size_t)Mpad * HCc];   // fp16 xl copy
__device__ __align__(16) __nv_bfloat16 g_wh[WTOT];
__device__ __align__(16) __nv_bfloat16 g_wl[WTOT];
__device__ float g_biascat[BTOT];
__device__ float g_big[(size_t)Mpad * 1152];
__device__ int   g_deg[Nn + 1];
__device__ int   g_indptr[Nn + 1];
__device__ int   g_cursor[Nn];
__device__ int   g_esrc[EA + 8];               // src node per CSR slot (+8 pad)
__device__ float g_pool[NGg * Cc];

// ---------------- PTX helpers (plain sm_80+ features only) ----------------
__device__ __forceinline__ uint32_t smem_u32(const void* p) {
    uint32_t a;
    asm("{ .reg .u64 t; cvta.to.shared.u64 t, %1; cvt.u32.u64 %0, t; }" : "=r"(a) : "l"(p));
    return a;
}
#define CPASY16(dst, src) asm volatile("cp.async.cg.shared.global [%0], [%1], 16;" :: "r"(dst), "l"(src))
#define CPASY_COMMIT()    asm volatile("cp.async.commit_group;" ::: "memory")
#define CPASY_WAIT1()     asm volatile("cp.async.wait_group 1;" ::: "memory")
#define CPASY_WAIT0()     asm volatile("cp.async.wait_group 0;" ::: "memory")

__device__ __forceinline__ void ldm_x4(uint32_t* r, uint32_t addr) {
    asm volatile("ldmatrix.sync.aligned.m8n8.x4.shared.b16 {%0,%1,%2,%3}, [%4];"
        : "=r"(r[0]), "=r"(r[1]), "=r"(r[2]), "=r"(r[3]) : "r"(addr));
}
__device__ __forceinline__ void mma_bf16(float* d, const uint32_t* a,
                                         uint32_t b0, uint32_t b1) {
    asm volatile("mma.sync.aligned.m16n8k16.row.col.f32.bf16.bf16.f32 "
        "{%0,%1,%2,%3}, {%4,%5,%6,%7}, {%8,%9}, {%0,%1,%2,%3};"
        : "+f"(d[0]), "+f"(d[1]), "+f"(d[2]), "+f"(d[3])
        : "r"(a[0]), "r"(a[1]), "r"(a[2]), "r"(a[3]), "r"(b0), "r"(b1));
}

// ---------------- consolidated prep: clears + weight split + bias concat ----------------
__global__ void prep_all(
    const float* __restrict__ inpw,
    const float* __restrict__ l0wl, const float* __restrict__ l0wr,
    const float* __restrict__ l1wl, const float* __restrict__ l1wr,
    const float* __restrict__ l2wl, const float* __restrict__ l2wr,
    const float* __restrict__ resw,
    const float* __restrict__ inpb,
    const float* __restrict__ l0bl, const float* __restrict__ l0br,
    const float* __restrict__ l1bl, const float* __restrict__ l1br,
    const float* __restrict__ l2bl, const float* __restrict__ l2br)
{
    int idx = blockIdx.x * blockDim.x + threadIdx.x;
    if (idx < 8) g_esrc[EA + idx] = 0;   // prefetch pad
    if (idx < WTOT) {
        float v;
        if (idx < W1OFF) {                       // W0: 1152 x 128
            int ng = idx >> 7, k = idx & 127;
            int sub = ng / 384, nl = ng - sub * 384;
            const float* w = (sub == 0) ? inpw : (sub == 1) ? l0wl : l0wr;
            v = w[k * 384 + nl];
        } else if (idx < W2OFF) {                // W1: 768 x 384
            int rem = idx - W1OFF;
            int ng = rem / 384, k = rem - ng * 384;
            const float* w = (ng < 384) ? l1wl : l1wr;
            int nl = (ng < 384) ? ng : ng - 384;
            v = w[k * 384 + nl];
        } else {                                 // W2: 256 x 384 (pad >=192)
            int rem = idx - W2OFF;
            int ng = rem / 384, k = rem - ng * 384;
            if      (ng < 64)  v = l2wl[k * 64 + ng];
            else if (ng < 128) v = l2wr[k * 64 + ng - 64];
            else if (ng < 192) v = resw[k * 64 + ng - 128];
            else               v = 0.f;
        }
        __nv_bfloat16 hi = __float2bfloat16(v);
        g_wh[idx] = hi;
        g_wl[idx] = __float2bfloat16(v - __bfloat162float(hi));
        return;
    }
    int r = idx - WTOT;
    if (r < BTOT) {
        float v = 0.f;
        if      (r < 384)  v = inpb[r];
        else if (r < 768)  v = l0bl[r - 384];
        else if (r < 1152) v = l0br[r - 768];
        else if (r < 1536) v = l1bl[r - 1152];
        else if (r < 1920) v = l1br[r - 1536];
        else if (r < 1984) v = l2bl[r - 1920];
        else if (r < 2048) v = l2br[r - 1984];
        g_biascat[r] = v;
        return;
    }
    r -= BTOT;
    if (r < Nn) { g_deg[r] = 0; return; }
    r -= Nn;
    if (r < NGg * Cc) g_pool[r] = 0.f;
}
#define PREP_TOT (WTOT + BTOT + Nn + NGg * Cc)

// ---------------- CSR build ----------------
__global__ void csr_count(const int* __restrict__ ei) {
    int e = blockIdx.x * blockDim.x + threadIdx.x;
    if (e >= EA) return;
    int d = (e < Ee) ? ei[Ee + e] : (e - Ee);
    atomicAdd(&g_deg[d], 1);
}

__global__ void csr_scan() {
    __shared__ int part[1024];
    const int per = (Nn + 1023) / 1024;
    int t = threadIdx.x;
    int s = 0;
    #pragma unroll
    for (int k = 0; k < per; ++k) { int i = t * per + k; if (i < Nn) s += g_deg[i]; }
    part[t] = s;
    __syncthreads();
    for (int off = 1; off < 1024; off <<= 1) {
        int v = (t >= off) ? part[t - off] : 0;
        __syncthreads();
        part[t] += v;
        __syncthreads();
    }
    int run = part[t] - s;
    #pragma unroll
    for (int k = 0; k < per; ++k) {
        int i = t * per + k;
        if (i < Nn) { g_indptr[i] = run; g_cursor[i] = run; run += g_deg[i]; }
    }
    if (t == 0) g_indptr[Nn] = EA;
}

__global__ void csr_scatter(const int* __restrict__ ei) {
    int e = blockIdx.x * blockDim.x + threadIdx.x;
    if (e >= EA) return;
    int s, d;
    if (e < Ee) { s = ei[e]; d = ei[Ee + e]; }
    else        { s = d = e - Ee; }
    int pos = atomicAdd(&g_cursor[d], 1);
    g_esrc[pos] = s;
}

// fp32 -> (hi, lo) bf16 split (layer-0 input only)
__global__ void conv_hilo(const float* __restrict__ src, int n4) {
    int i = blockIdx.x * blockDim.x + threadIdx.x;
    if (i >= n4) return;
    float4 v = reinterpret_cast<const float4*>(src)[i];
    __nv_bfloat16 h0 = __float2bfloat16(v.x), h1 = __float2bfloat16(v.y);
    __nv_bfloat16 h2 = __float2bfloat16(v.z), h3 = __float2bfloat16(v.w);
    g_ah[i * 4 + 0] = h0; g_ah[i * 4 + 1] = h1;
    g_ah[i * 4 + 2] = h2; g_ah[i * 4 + 3] = h3;
    g_al[i * 4 + 0] = __float2bfloat16(v.x - __bfloat162float(h0));
    g_al[i * 4 + 1] = __float2bfloat16(v.y - __bfloat162float(h1));
    g_al[i * 4 + 2] = __float2bfloat16(v.z - __bfloat162float(h2));
    g_al[i * 4 + 3] = __float2bfloat16(v.w - __bfloat162float(h3));
}

// ---------------- HMMA split-bf16 GEMM, 4-buffer single-K-pass ----------------
#define PADK 40
#define TILEB (128 * PADK * 2)     // 10240 bytes per tile
#define STAGEB (4 * TILEB)         // 40960 bytes per stage
#define SMEM_MM (2 * STAGEB)       // 81920

__global__ __launch_bounds__(256, 2) void mm_mma(
    const __nv_bfloat16* __restrict__ Ah, const __nv_bfloat16* __restrict__ Al,
    const __nv_bfloat16* __restrict__ Bh, const __nv_bfloat16* __restrict__ Bl,
    const float* __restrict__ bias, float* __restrict__ out,
    __half* __restrict__ hout, int hld, int hcol0, int hcolw,
    int K, int ldout)
{
    extern __shared__ __align__(16) char dsm[];
    uint32_t sbase = smem_u32(dsm);
    int tid = threadIdx.x, wid = tid >> 5, lane = tid & 31;
    int m0 = blockIdx.y * 128, n0 = blockIdx.x * 128;
    int warp_m = wid & 3, warp_n = wid >> 2;
    int nk = K >> 5;

    auto load_chunk = [&](int stage, int k0) {
        uint32_t dst0 = sbase + stage * STAGEB;
        #pragma unroll
        for (int it = 0; it < 8; ++it) {
            int idx = tid + it * 256;
            int buf = idx >> 9;
            int w   = idx & 511;
            int r   = w >> 2, q = w & 3;
            const __nv_bfloat16* src;
            if      (buf == 0) src = Ah + (size_t)(m0 + r) * K + k0 + q * 8;
            else if (buf == 1) src = Al + (size_t)(m0 + r) * K + k0 + q * 8;
            else if (buf == 2) src = Bh + (size_t)(n0 + r) * K + k0 + q * 8;
            else               src = Bl + (size_t)(n0 + r) * K + k0 + q * 8;
            CPASY16(dst0 + buf * TILEB + (r * PADK + q * 8) * 2, src);
        }
        CPASY_COMMIT();
    };

    load_chunk(0, 0);

    float acc[2][8][4];
    #pragma unroll
    for (int mi = 0; mi < 2; ++mi)
        #pragma unroll
        for (int nt = 0; nt < 8; ++nt)
            #pragma unroll
            for (int q = 0; q < 4; ++q) acc[mi][nt][q] = 0.f;

    int gA = lane >> 3, lrA = lane & 7;

    for (int c = 0; c < nk; ++c) {
        int s = c & 1;
        if (c + 1 < nk) { load_chunk(s ^ 1, (c + 1) << 5); CPASY_WAIT1(); }
        else            { CPASY_WAIT0(); }
        __syncthreads();

        uint32_t st = sbase + s * STAGEB;
        uint32_t aH = st + (warp_m * 32) * PADK * 2;
        uint32_t aL = st + TILEB + (warp_m * 32) * PADK * 2;
        uint32_t bH = st + 2 * TILEB + (warp_n * 64) * PADK * 2;
        uint32_t bL = st + 3 * TILEB + (warp_n * 64) * PADK * 2;

        #pragma unroll
        for (int kk = 0; kk < 32; kk += 16) {
            uint32_t afrH[2][4], afrL[2][4];
            #pragma unroll
            for (int mi = 0; mi < 2; ++mi) {
                int row = mi * 16 + ((gA & 1) << 3) + lrA;
                int col = ((gA >> 1) << 3) + kk;
                ldm_x4(afrH[mi], aH + (row * PADK + col) * 2);
                ldm_x4(afrL[mi], aL + (row * PADK + col) * 2);
            }
            uint32_t bfr[4][4];
            #pragma unroll
            for (int nb = 0; nb < 4; ++nb) {
                int n = nb * 16 + ((gA >> 1) << 3) + lrA;
                int col = ((gA & 1) << 3) + kk;
                ldm_x4(bfr[nb], bH + (n * PADK + col) * 2);
            }
            #pragma unroll
            for (int mi = 0; mi < 2; ++mi)
                #pragma unroll
                for (int nt = 0; nt < 8; ++nt) {
                    mma_bf16(acc[mi][nt], afrH[mi],
                             bfr[nt >> 1][(nt & 1) * 2], bfr[nt >> 1][(nt & 1) * 2 + 1]);
                    mma_bf16(acc[mi][nt], afrL[mi],
                             bfr[nt >> 1][(nt & 1) * 2], bfr[nt >> 1][(nt & 1) * 2 + 1]);
                }
            #pragma unroll
            for (int nb = 0; nb < 4; ++nb) {
                int n = nb * 16 + ((gA >> 1) << 3) + lrA;
                int col = ((gA & 1) << 3) + kk;
                ldm_x4(bfr[nb], bL + (n * PADK + col) * 2);
            }
            #pragma unroll
            for (int mi = 0; mi < 2; ++mi)
                #pragma unroll
                for (int nt = 0; nt < 8; ++nt)
                    mma_bf16(acc[mi][nt], afrH[mi],
                             bfr[nt >> 1][(nt & 1) * 2], bfr[nt >> 1][(nt & 1) * 2 + 1]);
        }
        __syncthreads();
    }

    int rl = lane >> 2, cl = (lane & 3) * 2;
    #pragma unroll
    for (int mi = 0; mi < 2; ++mi) {
        int r0 = m0 + warp_m * 32 + mi * 16 + rl;
        #pragma unroll
        for (int nt = 0; nt < 8; ++nt) {
            int cb = n0 + warp_n * 64 + nt * 8 + cl;
            float b0 = bias[cb], b1 = bias[cb + 1];
            bool inh = (unsigned)(cb - hcol0) < (unsigned)hcolw;
            int hc = cb - hcol0;
            if (r0 < Nn) {
                float v0 = acc[mi][nt][0] + b0, v1 = acc[mi][nt][1] + b1;
                if (inh)
                    *reinterpret_cast<__half2*>(&hout[(size_t)r0 * hld + hc]) = __floats2half2_rn(v0, v1);
                else {
                    float2 v = { v0, v1 };
                    *reinterpret_cast<float2*>(&out[(size_t)r0 * ldout + cb]) = v;
                }
            }
            if (r0 + 8 < Nn) {
                float v0 = acc[mi][nt][2] + b0, v1 = acc[mi][nt][3] + b1;
                if (inh)
                    *reinterpret_cast<__half2*>(&hout[(size_t)(r0 + 8) * hld + hc]) = __floats2half2_rn(v0, v1);
                else {
                    float2 v = { v0, v1 };
                    *reinterpret_cast<float2*>(&out[(size_t)(r0 + 8) * ldout + cb]) = v;
                }
            }
        }
    }
}

// ---------------- fused GATv2: convergent 2-edge half-warp version ----------------
// Warp per (node, head). All 32 lanes iterate the SAME j loop (j += 2);
// half h = lane>>4 handles edge j+h (invalid edge -> weight 0). Lane covers
// 4 channels (one 8B fp16 load). Reduce: 4 shfl levels within 16-lane half
// (full-warp convergent); 1 shfl level combines halves at the end.
__global__ void gat_fused(
    const __half* __restrict__ xh, int xld4,
    const float* __restrict__ big, int ld, int offR,
    const float* __restrict__ att, const float* __restrict__ bias,
    const float* __restrict__ resf, int ldresf,
    const __nv_bfloat16* __restrict__ resh, const __nv_bfloat16* __restrict__ resl, int ldresb,
    float* __restrict__ outf, int ldoutf,
    __nv_bfloat16* __restrict__ outh, __nv_bfloat16* __restrict__ outl,
    const int* __restrict__ pool_batch, int H, int npb)
{
    int wid = threadIdx.x >> 5;
    int lane = threadIdx.x & 31;
    int node = blockIdx.x * npb + wid / H;
    int head = wid - (wid / H) * H;
    if (node >= Nn) return;
    int h = lane >> 4, gl = lane & 15;
    int beg = g_indptr[node], end = g_indptr[node + 1];
    int c0 = head * 64 + gl * 4;

    float4 af = *reinterpret_cast<const float4*>(att + c0);
    __half2 ah[2] = { __floats2half2_rn(af.x, af.y), __floats2half2_rn(af.z, af.w) };
    float4 rf = *reinterpret_cast<const float4*>(big + (size_t)node * ld + offR + c0);
    __half2 xrh[2] = { __floats2half2_rn(rf.x, rf.y), __floats2half2_rn(rf.z, rf.w) };
    const __half2 p2 = __floats2half2_rn(0.2f, 0.2f);

    const uint2* xb = reinterpret_cast<const uint2*>(xh);
    int coff = head * 16 + gl;

    float ssum = 0.f;
    float acc[4] = {};
    uint2 hv_next = xb[(size_t)g_esrc[beg + h] * xld4 + coff];   // esrc padded -> safe

    for (int j = beg; j < end; j += 2) {
        uint2 hv = hv_next;
        hv_next = xb[(size_t)g_esrc[j + 2 + h] * xld4 + coff];
        const __half2* xvh = reinterpret_cast<const __half2*>(&hv);
        __half2 t0 = __hadd2(xvh[0], xrh[0]);
        __half2 t1 = __hadd2(xvh[1], xrh[1]);
        t0 = __hmax2(t0, __hmul2(t0, p2));           // leaky_relu(0.2)
        t1 = __hmax2(t1, __hmul2(t1, p2));
        __half2 dot = __hmul2(ah[0], t0);
        dot = __hfma2(ah[1], t1, dot);
        float p = __low2float(dot) + __high2float(dot);
        p += __shfl_xor_sync(0xffffffffu, p, 1);
        p += __shfl_xor_sync(0xffffffffu, p, 2);
        p += __shfl_xor_sync(0xffffffffu, p, 4);
        p += __shfl_xor_sync(0xffffffffu, p, 8);
        float w = (j + h < end) ? __expf(p) : 0.f;
        ssum += w;
        float2 x0 = __half22float2(xvh[0]);
        float2 x1 = __half22float2(xvh[1]);
        acc[0] = fmaf(w, x0.x, acc[0]);
        acc[1] = fmaf(w, x0.y, acc[1]);
        acc[2] = fmaf(w, x1.x, acc[2]);
        acc[3] = fmaf(w, x1.y, acc[3]);
    }
    // combine the two halves (loop is convergent; single shfl level)
    ssum += __shfl_xor_sync(0xffffffffu, ssum, 16);
    #pragma unroll
    for (int k = 0; k < 4; ++k)
        acc[k] += __shfl_xor_sync(0xffffffffu, acc[k], 16);
    if (h != 0) return;

    float inv = 1.f / (ssum + 1e-16f);
    float4 bf4 = *reinterpret_cast<const float4*>(bias + c0);
    float bb[4] = { bf4.x, bf4.y, bf4.z, bf4.w };
    float v[4];
    #pragma unroll
    for (int k = 0; k < 4; ++k) {
        float t = acc[k] * inv + bb[k];
        v[k] = (t > 0.f) ? t : (__expf(t) - 1.f);        // ELU
    }
    if (resf) {
        float4 q = *reinterpret_cast<const float4*>(resf + (size_t)node * ldresf + c0);
        v[0] += q.x; v[1] += q.y; v[2] += q.z; v[3] += q.w;
    } else {
        uint2 rhu = *reinterpret_cast<const uint2*>(resh + (size_t)node * ldresb + c0);
        uint2 rlu = *reinterpret_cast<const uint2*>(resl + (size_t)node * ldresb + c0);
        const __nv_bfloat162* rh2 = reinterpret_cast<const __nv_bfloat162*>(&rhu);
        const __nv_bfloat162* rl2 = reinterpret_cast<const __nv_bfloat162*>(&rlu);
        #pragma unroll
        for (int k = 0; k < 2; ++k) {
            float2 fh = __bfloat1622float2(rh2[k]);
            float2 fl = __bfloat1622float2(rl2[k]);
            v[2 * k]     += fh.x + fl.x;
            v[2 * k + 1] += fh.y + fl.y;
        }
    }
    if (outf)
        *reinterpret_cast<float4*>(outf + (size_t)node * ldoutf + c0) =
            make_float4(v[0], v[1], v[2], v[3]);
    if (outh) {
        __nv_bfloat162 hv2[2], lv2[2];
        #pragma unroll
        for (int k = 0; k < 2; ++k) {
            __nv_bfloat16 b0 = __float2bfloat16(v[2 * k]), b1 = __float2bfloat16(v[2 * k + 1]);
            hv2[k].x = b0; hv2[k].y = b1;
            lv2[k].x = __float2bfloat16(v[2 * k] - __bfloat162float(b0));
            lv2[k].y = __float2bfloat16(v[2 * k + 1] - __bfloat162float(b1));
        }
        *reinterpret_cast<uint2*>(outh + (size_t)node * HCc + c0) = *reinterpret_cast<uint2*>(hv2);
        *reinterpret_cast<uint2*>(outl + (size_t)node * HCc + c0) = *reinterpret_cast<uint2*>(lv2);
    }
    if (pool_batch) {                              // fused graph pooling (layer 2)
        int g = pool_batch[node];
        #pragma unroll
        for (int k = 0; k < 4; ++k)
            atomicAdd(&g_pool[g * Cc + c0 + k], v[k]);
    }
}

// ---------------- dense head ----------------
__global__ __launch_bounds__(1024) void dense_head(
    const float* __restrict__ d1w, const float* __restrict__ d1b,
    const float* __restrict__ bng, const float* __restrict__ bnb,
    const float* __restrict__ bnm, const float* __restrict__ bnv,
    const float* __restrict__ d2w, const float* __restrict__ d2b,
    float* __restrict__ z)
{
    __shared__ float sp[NGg * Cc];
    __shared__ float t1[NGg * Cc];
    int tid = threadIdx.x;
    for (int idx = tid; idx < NGg * Cc; idx += 1024) sp[idx] = g_pool[idx];
    __syncthreads();
    for (int idx = tid; idx < NGg * Cc; idx += 1024) {
        int r = idx >> 6, c = idx & 63;
        float s = d1b[c];
        #pragma unroll
        for (int k = 0; k < 64; ++k) s = fmaf(sp[r * 64 + k], d1w[k * 64 + c], s);
        s = (s - bnm[c]) * rsqrtf(bnv[c] + 1e-5f) * bng[c] + bnb[c];
        t1[idx] = (s > 0.f) ? s : 0.f;
    }
    __syncthreads();
    for (int idx = tid; idx < NGg * NCc; idx += 1024) {
        int r = idx >> 4, c = idx & 15;
        float s = d2b[c];
        #pragma unroll
        for (int k = 0; k < 64; ++k) s = fmaf(t1[r * 64 + k], d2w[k * 16 + c], s);
        z[idx] = s;
    }
}

// ---------------- host launcher ----------------
extern "C" void kernel_launch(void* const* d_in, const int* in_sizes, int n_in,
                              void* d_out, int out_size)
{
    const float* x      = (const float*)d_in[0];
    const int*   ei     = (const int*)  d_in[1];
    const int*   batch  = (const int*)  d_in[2];
    const float* inp_w  = (const float*)d_in[3];
    const float* inp_b  = (const float*)d_in[4];
    const float* l0_wl  = (const float*)d_in[5];
    const float* l0_bl  = (const float*)d_in[6];
    const float* l0_wr  = (const float*)d_in[7];
    const float* l0_br  = (const float*)d_in[8];
    const float* l0_att = (const float*)d_in[9];
    const float* l0_bias= (const float*)d_in[10];
    const float* l1_wl  = (const float*)d_in[11];
    const float* l1_bl  = (const float*)d_in[12];
    const float* l1_wr  = (const float*)d_in[13];
    const float* l1_br  = (const float*)d_in[14];
    const float* l1_att = (const float*)d_in[15];
    const float* l1_bias= (const float*)d_in[16];
    const float* l2_wl  = (const float*)d_in[17];
    const float* l2_bl  = (const float*)d_in[18];
    const float* l2_wr  = (const float*)d_in[19];
    const float* l2_br  = (const float*)d_in[20];
    const float* l2_att = (const float*)d_in[21];
    const float* l2_bias= (const float*)d_in[22];
    const float* res_w  = (const float*)d_in[23];
    const float* d1_w   = (const float*)d_in[24];
    const float* d1_b   = (const float*)d_in[25];
    const float* bn_g   = (const float*)d_in[26];
    const float* bn_b   = (const float*)d_in[27];
    const float* bn_m   = (const float*)d_in[28];
    const float* bn_v   = (const float*)d_in[29];
    const float* d2_w   = (const float*)d_in[30];
    const float* d2_b   = (const float*)d_in[31];
    float* out = (float*)d_out;

    float *p_big, *p_bias;
    __nv_bfloat16 *p_ah, *p_al, *p_wh, *p_wl;
    __half *p_hf;
    cudaGetSymbolAddress((void**)&p_big,  g_big);
    cudaGetSymbolAddress((void**)&p_ah,   g_ah);
    cudaGetSymbolAddress((void**)&p_al,   g_al);
    cudaGetSymbolAddress((void**)&p_wh,   g_wh);
    cudaGetSymbolAddress((void**)&p_wl,   g_wl);
    cudaGetSymbolAddress((void**)&p_hf,   g_hf);
    cudaGetSymbolAddress((void**)&p_bias, g_biascat);

    cudaFuncSetAttribute(mm_mma, cudaFuncAttributeMaxDynamicSharedMemorySize, SMEM_MM);

    // ---- consolidated prep + CSR build ----
    prep_all<<<(PREP_TOT + 255) / 256, 256>>>(
        inp_w, l0_wl, l0_wr, l1_wl, l1_wr, l2_wl, l2_wr, res_w,
        inp_b, l0_bl, l0_br, l1_bl, l1_br, l2_bl, l2_br);
    csr_count<<<(EA + 255) / 256, 256>>>(ei);
    csr_scan<<<1, 1024>>>();
    csr_scatter<<<(EA + 255) / 256, 256>>>(ei);

    const int MB = 157;  // ceil(20000/128)

    // ---- layer 0: fused GEMM [x_res | xl | xr], K=128, Ntot=1152 ----
    conv_hilo<<<(Nn * 128 / 4 + 255) / 256, 256>>>(x, Nn * 128 / 4);
    mm_mma<<<dim3(9, MB), 256, SMEM_MM>>>(p_ah, p_al, p_wh + W0OFF, p_wl + W0OFF,
                                          p_bias + B0OFF, p_big,
                                          p_hf, 384, 384, 384, 128, 1152);
    gat_fused<<<Nn, 32 * Hh>>>(p_hf, 96, p_big, 1152, 768, l0_att, l0_bias,
                               p_big, 1152, nullptr, nullptr, 0,
                               nullptr, 0, p_ah, p_al, nullptr, Hh, 1);   // h0 -> ah/al

    // ---- layer 1: fused GEMM [xl | xr], K=384, Ntot=768 ----
    mm_mma<<<dim3(6, MB), 256, SMEM_MM>>>(p_ah, p_al, p_wh + W1OFF, p_wl + W1OFF,
                                          p_bias + B1OFF, p_big,
                                          p_hf, 384, 0, 384, 384, 768);
    gat_fused<<<Nn, 32 * Hh>>>(p_hf, 96, p_big, 768, 384, l1_att, l1_bias,
                               nullptr, 0, p_ah, p_al, HCc,
                               nullptr, 0, p_ah, p_al, nullptr, Hh, 1);   // res=h0, h1 -> ah/al

    // ---- layer 2: fused GEMM [xl | xr | res_proj | pad], K=384, Ntot=256 ----
    mm_mma<<<dim3(2, MB), 256, SMEM_MM>>>(p_ah, p_al, p_wh + W2OFF, p_wl + W2OFF,
                                          p_bias + B2OFF, p_big,
                                          p_hf, 64, 0, 64, 384, 256);
    gat_fused<<<(Nn + 7) / 8, 256>>>(p_hf, 16, p_big, 256, 64, l2_att, l2_bias,
                                     p_big + 128, 256, nullptr, nullptr, 0,
                                     out, 64, nullptr, nullptr, batch, 1, 8);  // h -> d_out, fused pool

    // ---- dense head ----
    dense_head<<<1, 1024>>>(d1_w, d1_b, bn_g, bn_b, bn_m, bn_v, d2_w, d2_b,
                            out + (size_t)Nn * Cc);
}

// round 13
// speedup vs baseline: 1.0978x; 1.0466x over previous
#include <cuda_runtime.h>
#include <cuda_bf16.h>
#include <cuda_fp16.h>
#include <cstdint>
#include <math.h>

// Problem constants
#define Nn    20000
#define Mpad  20096            // 157 * 128
#define Ee    320000
#define EA    (Ee + Nn)
#define INF_  128
#define Hh    6
#define Cc    64
#define HCc   384
#define NGg   64
#define NCc   16

// weight-prep element offsets in concatenated [N x K] K-major bf16 buffers
#define W0OFF 0                // layer0: 1152 x 128
#define W1OFF 147456           // layer1: 768 x 384
#define W2OFF 442368           // layer2: 256 x 384 (rows 192..255 zero pad)
#define WTOT  540672
#define B0OFF 0
#define B1OFF 1152
#define B2OFF 1920
#define BTOT  2176

// ---------------- device scratch ----------------
__device__ __align__(16) __nv_bfloat16 g_ah[(size_t)Mpad * HCc];
__device__ __align__(16) __nv_bfloat16 g_al[(size_t)Mpad * HCc];
__device__ __align__(16) __half        g_hf[(size_t)Mpad * HCc];   // fp16 xl copy
__device__ __align__(16) __nv_bfloat16 g_wh[WTOT];
__device__ __align__(16) __nv_bfloat16 g_wl[WTOT];
__device__ float g_biascat[BTOT];
__device__ float g_big[(size_t)Mpad * 1152];
__device__ int   g_deg[Nn + 1];
__device__ int   g_indptr[Nn + 1];
__device__ int   g_cursor[Nn];
__device__ int   g_esrc[EA + 8];               // src node per CSR slot (+8 pad)
__device__ float g_pool[NGg * Cc];

// ---------------- PTX helpers (plain sm_80+ features only) ----------------
__device__ __forceinline__ uint32_t smem_u32(const void* p) {
    uint32_t a;
    asm("{ .reg .u64 t; cvta.to.shared.u64 t, %1; cvt.u32.u64 %0, t; }" : "=r"(a) : "l"(p));
    return a;
}
#define CPASY16(dst, src) asm volatile("cp.async.cg.shared.global [%0], [%1], 16;" :: "r"(dst), "l"(src))
#define CPASY_COMMIT()    asm volatile("cp.async.commit_group;" ::: "memory")
#define CPASY_WAIT1()     asm volatile("cp.async.wait_group 1;" ::: "memory")
#define CPASY_WAIT0()     asm volatile("cp.async.wait_group 0;" ::: "memory")

__device__ __forceinline__ void ldm_x4(uint32_t* r, uint32_t addr) {
    asm volatile("ldmatrix.sync.aligned.m8n8.x4.shared.b16 {%0,%1,%2,%3}, [%4];"
        : "=r"(r[0]), "=r"(r[1]), "=r"(r[2]), "=r"(r[3]) : "r"(addr));
}
__device__ __forceinline__ void mma_bf16(float* d, const uint32_t* a,
                                         uint32_t b0, uint32_t b1) {
    asm volatile("mma.sync.aligned.m16n8k16.row.col.f32.bf16.bf16.f32 "
        "{%0,%1,%2,%3}, {%4,%5,%6,%7}, {%8,%9}, {%0,%1,%2,%3};"
        : "+f"(d[0]), "+f"(d[1]), "+f"(d[2]), "+f"(d[3])
        : "r"(a[0]), "r"(a[1]), "r"(a[2]), "r"(a[3]), "r"(b0), "r"(b1));
}

// ---------------- prep: weight split + bias concat (stream A) ----------------
__global__ void prep_all(
    const float* __restrict__ inpw,
    const float* __restrict__ l0wl, const float* __restrict__ l0wr,
    const float* __restrict__ l1wl, const float* __restrict__ l1wr,
    const float* __restrict__ l2wl, const float* __restrict__ l2wr,
    const float* __restrict__ resw,
    const float* __restrict__ inpb,
    const float* __restrict__ l0bl, const float* __restrict__ l0br,
    const float* __restrict__ l1bl, const float* __restrict__ l1br,
    const float* __restrict__ l2bl, const float* __restrict__ l2br)
{
    int idx = blockIdx.x * blockDim.x + threadIdx.x;
    if (idx < WTOT) {
        float v;
        if (idx < W1OFF) {                       // W0: 1152 x 128
            int ng = idx >> 7, k = idx & 127;
            int sub = ng / 384, nl = ng - sub * 384;
            const float* w = (sub == 0) ? inpw : (sub == 1) ? l0wl : l0wr;
            v = w[k * 384 + nl];
        } else if (idx < W2OFF) {                // W1: 768 x 384
            int rem = idx - W1OFF;
            int ng = rem / 384, k = rem - ng * 384;
            const float* w = (ng < 384) ? l1wl : l1wr;
            int nl = (ng < 384) ? ng : ng - 384;
            v = w[k * 384 + nl];
        } else {                                 // W2: 256 x 384 (pad >=192)
            int rem = idx - W2OFF;
            int ng = rem / 384, k = rem - ng * 384;
            if      (ng < 64)  v = l2wl[k * 64 + ng];
            else if (ng < 128) v = l2wr[k * 64 + ng - 64];
            else if (ng < 192) v = resw[k * 64 + ng - 128];
            else               v = 0.f;
        }
        __nv_bfloat16 hi = __float2bfloat16(v);
        g_wh[idx] = hi;
        g_wl[idx] = __float2bfloat16(v - __bfloat162float(hi));
        return;
    }
    int r = idx - WTOT;
    if (r < BTOT) {
        float v = 0.f;
        if      (r < 384)  v = inpb[r];
        else if (r < 768)  v = l0bl[r - 384];
        else if (r < 1152) v = l0br[r - 768];
        else if (r < 1536) v = l1bl[r - 1152];
        else if (r < 1920) v = l1br[r - 1536];
        else if (r < 1984) v = l2bl[r - 1920];
        else if (r < 2048) v = l2br[r - 1984];
        g_biascat[r] = v;
    }
}
#define PREP_TOT (WTOT + BTOT)

// ---------------- CSR build (stream B) ----------------
__global__ void clearB() {     // deg + pool + esrc pad
    int i = blockIdx.x * blockDim.x + threadIdx.x;
    if (i < Nn) g_deg[i] = 0;
    if (i < NGg * Cc) g_pool[i] = 0.f;
    if (i < 8) g_esrc[EA + i] = 0;
}

__global__ void csr_count(const int* __restrict__ ei) {
    int e = blockIdx.x * blockDim.x + threadIdx.x;
    if (e >= EA) return;
    int d = (e < Ee) ? ei[Ee + e] : (e - Ee);
    atomicAdd(&g_deg[d], 1);
}

__global__ void csr_scan() {
    __shared__ int part[1024];
    const int per = (Nn + 1023) / 1024;
    int t = threadIdx.x;
    int s = 0;
    #pragma unroll
    for (int k = 0; k < per; ++k) { int i = t * per + k; if (i < Nn) s += g_deg[i]; }
    part[t] = s;
    __syncthreads();
    for (int off = 1; off < 1024; off <<= 1) {
        int v = (t >= off) ? part[t - off] : 0;
        __syncthreads();
        part[t] += v;
        __syncthreads();
    }
    int run = part[t] - s;
    #pragma unroll
    for (int k = 0; k < per; ++k) {
        int i = t * per + k;
        if (i < Nn) { g_indptr[i] = run; g_cursor[i] = run; run += g_deg[i]; }
    }
    if (t == 0) g_indptr[Nn] = EA;
}

__global__ void csr_scatter(const int* __restrict__ ei) {
    int e = blockIdx.x * blockDim.x + threadIdx.x;
    if (e >= EA) return;
    int s, d;
    if (e < Ee) { s = ei[e]; d = ei[Ee + e]; }
    else        { s = d = e - Ee; }
    int pos = atomicAdd(&g_cursor[d], 1);
    g_esrc[pos] = s;
}

// fp32 -> (hi, lo) bf16 split (layer-0 input only)
__global__ void conv_hilo(const float* __restrict__ src, int n4) {
    int i = blockIdx.x * blockDim.x + threadIdx.x;
    if (i >= n4) return;
    float4 v = reinterpret_cast<const float4*>(src)[i];
    __nv_bfloat16 h0 = __float2bfloat16(v.x), h1 = __float2bfloat16(v.y);
    __nv_bfloat16 h2 = __float2bfloat16(v.z), h3 = __float2bfloat16(v.w);
    g_ah[i * 4 + 0] = h0; g_ah[i * 4 + 1] = h1;
    g_ah[i * 4 + 2] = h2; g_ah[i * 4 + 3] = h3;
    g_al[i * 4 + 0] = __float2bfloat16(v.x - __bfloat162float(h0));
    g_al[i * 4 + 1] = __float2bfloat16(v.y - __bfloat162float(h1));
    g_al[i * 4 + 2] = __float2bfloat16(v.z - __bfloat162float(h2));
    g_al[i * 4 + 3] = __float2bfloat16(v.w - __bfloat162float(h3));
}

// ---------------- HMMA split-bf16 GEMM, 4-buffer single-K-pass ----------------
#define PADK 40
#define TILEB (128 * PADK * 2)     // 10240 bytes per tile
#define STAGEB (4 * TILEB)         // 40960 bytes per stage
#define SMEM_MM (2 * STAGEB)       // 81920

__global__ __launch_bounds__(256, 2) void mm_mma(
    const __nv_bfloat16* __restrict__ Ah, const __nv_bfloat16* __restrict__ Al,
    const __nv_bfloat16* __restrict__ Bh, const __nv_bfloat16* __restrict__ Bl,
    const float* __restrict__ bias, float* __restrict__ out,
    __half* __restrict__ hout, int hld, int hcol0, int hcolw,
    int K, int ldout)
{
    extern __shared__ __align__(16) char dsm[];
    uint32_t sbase = smem_u32(dsm);
    int tid = threadIdx.x, wid = tid >> 5, lane = tid & 31;
    int m0 = blockIdx.y * 128, n0 = blockIdx.x * 128;
    int warp_m = wid & 3, warp_n = wid >> 2;
    int nk = K >> 5;

    auto load_chunk = [&](int stage, int k0) {
        uint32_t dst0 = sbase + stage * STAGEB;
        #pragma unroll
        for (int it = 0; it < 8; ++it) {
            int idx = tid + it * 256;
            int buf = idx >> 9;
            int w   = idx & 511;
            int r   = w >> 2, q = w & 3;
            const __nv_bfloat16* src;
            if      (buf == 0) src = Ah + (size_t)(m0 + r) * K + k0 + q * 8;
            else if (buf == 1) src = Al + (size_t)(m0 + r) * K + k0 + q * 8;
            else if (buf == 2) src = Bh + (size_t)(n0 + r) * K + k0 + q * 8;
            else               src = Bl + (size_t)(n0 + r) * K + k0 + q * 8;
            CPASY16(dst0 + buf * TILEB + (r * PADK + q * 8) * 2, src);
        }
        CPASY_COMMIT();
    };

    load_chunk(0, 0);

    float acc[2][8][4];
    #pragma unroll
    for (int mi = 0; mi < 2; ++mi)
        #pragma unroll
        for (int nt = 0; nt < 8; ++nt)
            #pragma unroll
            for (int q = 0; q < 4; ++q) acc[mi][nt][q] = 0.f;

    int gA = lane >> 3, lrA = lane & 7;

    for (int c = 0; c < nk; ++c) {
        int s = c & 1;
        if (c + 1 < nk) { load_chunk(s ^ 1, (c + 1) << 5); CPASY_WAIT1(); }
        else            { CPASY_WAIT0(); }
        __syncthreads();

        uint32_t st = sbase + s * STAGEB;
        uint32_t aH = st + (warp_m * 32) * PADK * 2;
        uint32_t aL = st + TILEB + (warp_m * 32) * PADK * 2;
        uint32_t bH = st + 2 * TILEB + (warp_n * 64) * PADK * 2;
        uint32_t bL = st + 3 * TILEB + (warp_n * 64) * PADK * 2;

        #pragma unroll
        for (int kk = 0; kk < 32; kk += 16) {
            uint32_t afrH[2][4], afrL[2][4];
            #pragma unroll
            for (int mi = 0; mi < 2; ++mi) {
                int row = mi * 16 + ((gA & 1) << 3) + lrA;
                int col = ((gA >> 1) << 3) + kk;
                ldm_x4(afrH[mi], aH + (row * PADK + col) * 2);
                ldm_x4(afrL[mi], aL + (row * PADK + col) * 2);
            }
            uint32_t bfr[4][4];
            #pragma unroll
            for (int nb = 0; nb < 4; ++nb) {
                int n = nb * 16 + ((gA >> 1) << 3) + lrA;
                int col = ((gA & 1) << 3) + kk;
                ldm_x4(bfr[nb], bH + (n * PADK + col) * 2);
            }
            #pragma unroll
            for (int mi = 0; mi < 2; ++mi)
                #pragma unroll
                for (int nt = 0; nt < 8; ++nt) {
                    mma_bf16(acc[mi][nt], afrH[mi],
                             bfr[nt >> 1][(nt & 1) * 2], bfr[nt >> 1][(nt & 1) * 2 + 1]);
                    mma_bf16(acc[mi][nt], afrL[mi],
                             bfr[nt >> 1][(nt & 1) * 2], bfr[nt >> 1][(nt & 1) * 2 + 1]);
                }
            #pragma unroll
            for (int nb = 0; nb < 4; ++nb) {
                int n = nb * 16 + ((gA >> 1) << 3) + lrA;
                int col = ((gA & 1) << 3) + kk;
                ldm_x4(bfr[nb], bL + (n * PADK + col) * 2);
            }
            #pragma unroll
            for (int mi = 0; mi < 2; ++mi)
                #pragma unroll
                for (int nt = 0; nt < 8; ++nt)
                    mma_bf16(acc[mi][nt], afrH[mi],
                             bfr[nt >> 1][(nt & 1) * 2], bfr[nt >> 1][(nt & 1) * 2 + 1]);
        }
        __syncthreads();
    }

    int rl = lane >> 2, cl = (lane & 3) * 2;
    #pragma unroll
    for (int mi = 0; mi < 2; ++mi) {
        int r0 = m0 + warp_m * 32 + mi * 16 + rl;
        #pragma unroll
        for (int nt = 0; nt < 8; ++nt) {
            int cb = n0 + warp_n * 64 + nt * 8 + cl;
            float b0 = bias[cb], b1 = bias[cb + 1];
            bool inh = (unsigned)(cb - hcol0) < (unsigned)hcolw;
            int hc = cb - hcol0;
            if (r0 < Nn) {
                float v0 = acc[mi][nt][0] + b0, v1 = acc[mi][nt][1] + b1;
                if (inh)
                    *reinterpret_cast<__half2*>(&hout[(size_t)r0 * hld + hc]) = __floats2half2_rn(v0, v1);
                else {
                    float2 v = { v0, v1 };
                    *reinterpret_cast<float2*>(&out[(size_t)r0 * ldout + cb]) = v;
                }
            }
            if (r0 + 8 < Nn) {
                float v0 = acc[mi][nt][2] + b0, v1 = acc[mi][nt][3] + b1;
                if (inh)
                    *reinterpret_cast<__half2*>(&hout[(size_t)(r0 + 8) * hld + hc]) = __floats2half2_rn(v0, v1);
                else {
                    float2 v = { v0, v1 };
                    *reinterpret_cast<float2*>(&out[(size_t)(r0 + 8) * ldout + cb]) = v;
                }
            }
        }
    }
}

// ---------------- fused GATv2: convergent 2-edge half-warp version ----------------
__global__ void gat_fused(
    const __half* __restrict__ xh, int xld4,
    const float* __restrict__ big, int ld, int offR,
    const float* __restrict__ att, const float* __restrict__ bias,
    const float* __restrict__ resf, int ldresf,
    const __nv_bfloat16* __restrict__ resh, const __nv_bfloat16* __restrict__ resl, int ldresb,
    float* __restrict__ outf, int ldoutf,
    __nv_bfloat16* __restrict__ outh, __nv_bfloat16* __restrict__ outl,
    const int* __restrict__ pool_batch, int H, int npb)
{
    int wid = threadIdx.x >> 5;
    int lane = threadIdx.x & 31;
    int node = blockIdx.x * npb + wid / H;
    int head = wid - (wid / H) * H;
    if (node >= Nn) return;
    int h = lane >> 4, gl = lane & 15;
    int beg = g_indptr[node], end = g_indptr[node + 1];
    int c0 = head * 64 + gl * 4;

    float4 af = *reinterpret_cast<const float4*>(att + c0);
    __half2 ah[2] = { __floats2half2_rn(af.x, af.y), __floats2half2_rn(af.z, af.w) };
    float4 rf = *reinterpret_cast<const float4*>(big + (size_t)node * ld + offR + c0);
    __half2 xrh[2] = { __floats2half2_rn(rf.x, rf.y), __floats2half2_rn(rf.z, rf.w) };
    const __half2 p2 = __floats2half2_rn(0.2f, 0.2f);

    const uint2* xb = reinterpret_cast<const uint2*>(xh);
    int coff = head * 16 + gl;

    float ssum = 0.f;
    float acc[4] = {};
    uint2 hv_next = xb[(size_t)g_esrc[beg + h] * xld4 + coff];   // esrc padded -> safe

    for (int j = beg; j < end; j += 2) {
        uint2 hv = hv_next;
        hv_next = xb[(size_t)g_esrc[j + 2 + h] * xld4 + coff];
        const __half2* xvh = reinterpret_cast<const __half2*>(&hv);
        __half2 t0 = __hadd2(xvh[0], xrh[0]);
        __half2 t1 = __hadd2(xvh[1], xrh[1]);
        t0 = __hmax2(t0, __hmul2(t0, p2));           // leaky_relu(0.2)
        t1 = __hmax2(t1, __hmul2(t1, p2));
        __half2 dot = __hmul2(ah[0], t0);
        dot = __hfma2(ah[1], t1, dot);
        float p = __low2float(dot) + __high2float(dot);
        p += __shfl_xor_sync(0xffffffffu, p, 1);
        p += __shfl_xor_sync(0xffffffffu, p, 2);
        p += __shfl_xor_sync(0xffffffffu, p, 4);
        p += __shfl_xor_sync(0xffffffffu, p, 8);
        float w = (j + h < end) ? __expf(p) : 0.f;
        ssum += w;
        float2 x0 = __half22float2(xvh[0]);
        float2 x1 = __half22float2(xvh[1]);
        acc[0] = fmaf(w, x0.x, acc[0]);
        acc[1] = fmaf(w, x0.y, acc[1]);
        acc[2] = fmaf(w, x1.x, acc[2]);
        acc[3] = fmaf(w, x1.y, acc[3]);
    }
    ssum += __shfl_xor_sync(0xffffffffu, ssum, 16);
    #pragma unroll
    for (int k = 0; k < 4; ++k)
        acc[k] += __shfl_xor_sync(0xffffffffu, acc[k], 16);
    if (h != 0) return;

    float inv = 1.f / (ssum + 1e-16f);
    float4 bf4 = *reinterpret_cast<const float4*>(bias + c0);
    float bb[4] = { bf4.x, bf4.y, bf4.z, bf4.w };
    float v[4];
    #pragma unroll
    for (int k = 0; k < 4; ++k) {
        float t = acc[k] * inv + bb[k];
        v[k] = (t > 0.f) ? t : (__expf(t) - 1.f);        // ELU
    }
    if (resf) {
        float4 q = *reinterpret_cast<const float4*>(resf + (size_t)node * ldresf + c0);
        v[0] += q.x; v[1] += q.y; v[2] += q.z; v[3] += q.w;
    } else {
        uint2 rhu = *reinterpret_cast<const uint2*>(resh + (size_t)node * ldresb + c0);
        uint2 rlu = *reinterpret_cast<const uint2*>(resl + (size_t)node * ldresb + c0);
        const __nv_bfloat162* rh2 = reinterpret_cast<const __nv_bfloat162*>(&rhu);
        const __nv_bfloat162* rl2 = reinterpret_cast<const __nv_bfloat162*>(&rlu);
        #pragma unroll
        for (int k = 0; k < 2; ++k) {
            float2 fh = __bfloat1622float2(rh2[k]);
            float2 fl = __bfloat1622float2(rl2[k]);
            v[2 * k]     += fh.x + fl.x;
            v[2 * k + 1] += fh.y + fl.y;
        }
    }
    if (outf)
        *reinterpret_cast<float4*>(outf + (size_t)node * ldoutf + c0) =
            make_float4(v[0], v[1], v[2], v[3]);
    if (outh) {
        __nv_bfloat162 hv2[2], lv2[2];
        #pragma unroll
        for (int k = 0; k < 2; ++k) {
            __nv_bfloat16 b0 = __float2bfloat16(v[2 * k]), b1 = __float2bfloat16(v[2 * k + 1]);
            hv2[k].x = b0; hv2[k].y = b1;
            lv2[k].x = __float2bfloat16(v[2 * k] - __bfloat162float(b0));
            lv2[k].y = __float2bfloat16(v[2 * k + 1] - __bfloat162float(b1));
        }
        *reinterpret_cast<uint2*>(outh + (size_t)node * HCc + c0) = *reinterpret_cast<uint2*>(hv2);
        *reinterpret_cast<uint2*>(outl + (size_t)node * HCc + c0) = *reinterpret_cast<uint2*>(lv2);
    }
    if (pool_batch) {                              // fused graph pooling (layer 2)
        int g = pool_batch[node];
        #pragma unroll
        for (int k = 0; k < 4; ++k)
            atomicAdd(&g_pool[g * Cc + c0 + k], v[k]);
    }
}

// ---------------- dense head ----------------
__global__ __launch_bounds__(1024) void dense_head(
    const float* __restrict__ d1w, const float* __restrict__ d1b,
    const float* __restrict__ bng, const float* __restrict__ bnb,
    const float* __restrict__ bnm, const float* __restrict__ bnv,
    const float* __restrict__ d2w, const float* __restrict__ d2b,
    float* __restrict__ z)
{
    __shared__ float sp[NGg * Cc];
    __shared__ float t1[NGg * Cc];
    int tid = threadIdx.x;
    for (int idx = tid; idx < NGg * Cc; idx += 1024) sp[idx] = g_pool[idx];
    __syncthreads();
    for (int idx = tid; idx < NGg * Cc; idx += 1024) {
        int r = idx >> 6, c = idx & 63;
        float s = d1b[c];
        #pragma unroll
        for (int k = 0; k < 64; ++k) s = fmaf(sp[r * 64 + k], d1w[k * 64 + c], s);
        s = (s - bnm[c]) * rsqrtf(bnv[c] + 1e-5f) * bng[c] + bnb[c];
        t1[idx] = (s > 0.f) ? s : 0.f;
    }
    __syncthreads();
    for (int idx = tid; idx < NGg * NCc; idx += 1024) {
        int r = idx >> 4, c = idx & 15;
        float s = d2b[c];
        #pragma unroll
        for (int k = 0; k < 64; ++k) s = fmaf(t1[r * 64 + k], d2w[k * 16 + c], s);
        z[idx] = s;
    }
}

// ---------------- host launcher ----------------
extern "C" void kernel_launch(void* const* d_in, const int* in_sizes, int n_in,
                              void* d_out, int out_size)
{
    const float* x      = (const float*)d_in[0];
    const int*   ei     = (const int*)  d_in[1];
    const int*   batch  = (const int*)  d_in[2];
    const float* inp_w  = (const float*)d_in[3];
    const float* inp_b  = (const float*)d_in[4];
    const float* l0_wl  = (const float*)d_in[5];
    const float* l0_bl  = (const float*)d_in[6];
    const float* l0_wr  = (const float*)d_in[7];
    const float* l0_br  = (const float*)d_in[8];
    const float* l0_att = (const float*)d_in[9];
    const float* l0_bias= (const float*)d_in[10];
    const float* l1_wl  = (const float*)d_in[11];
    const float* l1_bl  = (const float*)d_in[12];
    const float* l1_wr  = (const float*)d_in[13];
    const float* l1_br  = (const float*)d_in[14];
    const float* l1_att = (const float*)d_in[15];
    const float* l1_bias= (const float*)d_in[16];
    const float* l2_wl  = (const float*)d_in[17];
    const float* l2_bl  = (const float*)d_in[18];
    const float* l2_wr  = (const float*)d_in[19];
    const float* l2_br  = (const float*)d_in[20];
    const float* l2_att = (const float*)d_in[21];
    const float* l2_bias= (const float*)d_in[22];
    const float* res_w  = (const float*)d_in[23];
    const float* d1_w   = (const float*)d_in[24];
    const float* d1_b   = (const float*)d_in[25];
    const float* bn_g   = (const float*)d_in[26];
    const float* bn_b   = (const float*)d_in[27];
    const float* bn_m   = (const float*)d_in[28];
    const float* bn_v   = (const float*)d_in[29];
    const float* d2_w   = (const float*)d_in[30];
    const float* d2_b   = (const float*)d_in[31];
    float* out = (float*)d_out;

    float *p_big, *p_bias;
    __nv_bfloat16 *p_ah, *p_al, *p_wh, *p_wl;
    __half *p_hf;
    cudaGetSymbolAddress((void**)&p_big,  g_big);
    cudaGetSymbolAddress((void**)&p_ah,   g_ah);
    cudaGetSymbolAddress((void**)&p_al,   g_al);
    cudaGetSymbolAddress((void**)&p_wh,   g_wh);
    cudaGetSymbolAddress((void**)&p_wl,   g_wl);
    cudaGetSymbolAddress((void**)&p_hf,   g_hf);
    cudaGetSymbolAddress((void**)&p_bias, g_biascat);

    cudaFuncSetAttribute(mm_mma, cudaFuncAttributeMaxDynamicSharedMemorySize, SMEM_MM);

    // fork CSR chain onto side stream (capture-legal fork/join)
    cudaStream_t sB;
    cudaStreamCreateWithFlags(&sB, cudaStreamNonBlocking);
    cudaEvent_t evFork, evJoin;
    cudaEventCreateWithFlags(&evFork, cudaEventDisableTiming);
    cudaEventCreateWithFlags(&evJoin, cudaEventDisableTiming);

    cudaEventRecord(evFork, 0);
    cudaStreamWaitEvent(sB, evFork, 0);
    clearB<<<(Nn + 255) / 256, 256, 0, sB>>>();
    csr_count<<<(EA + 255) / 256, 256, 0, sB>>>(ei);
    csr_scan<<<1, 1024, 0, sB>>>();
    csr_scatter<<<(EA + 255) / 256, 256, 0, sB>>>(ei);
    cudaEventRecord(evJoin, sB);

    // stream A: weight prep + layer-0 GEMM (independent of CSR)
    prep_all<<<(PREP_TOT + 255) / 256, 256>>>(
        inp_w, l0_wl, l0_wr, l1_wl, l1_wr, l2_wl, l2_wr, res_w,
        inp_b, l0_bl, l0_br, l1_bl, l1_br, l2_bl, l2_br);
    conv_hilo<<<(Nn * 128 / 4 + 255) / 256, 256>>>(x, Nn * 128 / 4);

    const int MB = 157;  // ceil(20000/128)

    mm_mma<<<dim3(9, MB), 256, SMEM_MM>>>(p_ah, p_al, p_wh + W0OFF, p_wl + W0OFF,
                                          p_bias + B0OFF, p_big,
                                          p_hf, 384, 384, 384, 128, 1152);
    cudaStreamWaitEvent(0, evJoin, 0);   // CSR ready before first gat
    gat_fused<<<Nn, 32 * Hh>>>(p_hf, 96, p_big, 1152, 768, l0_att, l0_bias,
                               p_big, 1152, nullptr, nullptr, 0,
                               nullptr, 0, p_ah, p_al, nullptr, Hh, 1);   // h0 -> ah/al

    mm_mma<<<dim3(6, MB), 256, SMEM_MM>>>(p_ah, p_al, p_wh + W1OFF, p_wl + W1OFF,
                                          p_bias + B1OFF, p_big,
                                          p_hf, 384, 0, 384, 384, 768);
    gat_fused<<<Nn, 32 * Hh>>>(p_hf, 96, p_big, 768, 384, l1_att, l1_bias,
                               nullptr, 0, p_ah, p_al, HCc,
                               nullptr, 0, p_ah, p_al, nullptr, Hh, 1);   // res=h0, h1 -> ah/al

    mm_mma<<<dim3(2, MB), 256, SMEM_MM>>>(p_ah, p_al, p_wh + W2OFF, p_wl + W2OFF,
                                          p_bias + B2OFF, p_big,
                                          p_hf, 64, 0, 64, 384, 256);
    gat_fused<<<(Nn + 7) / 8, 256>>>(p_hf, 16, p_big, 256, 64, l2_att, l2_bias,
                                     p_big + 128, 256, nullptr, nullptr, 0,
                                     out, 64, nullptr, nullptr, batch, 1, 8);  // h -> d_out, fused pool

    dense_head<<<1, 1024>>>(d1_w, d1_b, bn_g, bn_b, bn_m, bn_v, d2_w, d2_b,
                            out + (size_t)Nn * Cc);

    cudaEventDestroy(evFork);
    cudaEventDestroy(evJoin);
    cudaStreamDestroy(sB);
}

// round 14
// speedup vs baseline: 1.1533x; 1.0506x over previous
#include <cuda_runtime.h>
#include <cuda_bf16.h>
#include <cuda_fp16.h>
#include <cstdint>
#include <math.h>

// Problem constants
#define Nn    20000
#define Mpad  20096            // 157 * 128
#define Ee    320000
#define EA    (Ee + Nn)
#define INF_  128
#define Hh    6
#define Cc    64
#define HCc   384
#define NGg   64
#define NCc   16

// weight-prep element offsets in concatenated [N x K] K-major bf16 buffers
#define W0OFF 0                // layer0: 1152 x 128
#define W1OFF 147456           // layer1: 768 x 384
#define W2OFF 442368           // layer2: 256 x 384 (rows 192..255 zero pad)
#define WTOT  540672
#define B0OFF 0
#define B1OFF 1152
#define B2OFF 1920
#define BTOT  2176

// ---------------- device scratch ----------------
__device__ __align__(16) __nv_bfloat16 g_ah[(size_t)Mpad * HCc];
__device__ __align__(16) __nv_bfloat16 g_al[(size_t)Mpad * HCc];
__device__ __align__(16) __half        g_hf[(size_t)Mpad * 768];  // fp16 [xl|xr] copy
__device__ __align__(16) __nv_bfloat16 g_wh[WTOT];
__device__ __align__(16) __nv_bfloat16 g_wl[WTOT];
__device__ float g_biascat[BTOT];
__device__ float g_big[(size_t)Mpad * 384];    // fp32 region (x_res / res_proj only)
__device__ int   g_deg[Nn + 1];
__device__ int   g_indptr[Nn + 1];
__device__ int   g_cursor[Nn];
__device__ int   g_esrc[EA + 8];               // src node per CSR slot (+8 pad)
__device__ float g_pool[NGg * Cc];

// ---------------- PTX helpers (plain sm_80+ features only) ----------------
__device__ __forceinline__ uint32_t smem_u32(const void* p) {
    uint32_t a;
    asm("{ .reg .u64 t; cvta.to.shared.u64 t, %1; cvt.u32.u64 %0, t; }" : "=r"(a) : "l"(p));
    return a;
}
#define CPASY16(dst, src) asm volatile("cp.async.cg.shared.global [%0], [%1], 16;" :: "r"(dst), "l"(src))
#define CPASY_COMMIT()    asm volatile("cp.async.commit_group;" ::: "memory")
#define CPASY_WAIT1()     asm volatile("cp.async.wait_group 1;" ::: "memory")
#define CPASY_WAIT0()     asm volatile("cp.async.wait_group 0;" ::: "memory")

__device__ __forceinline__ void ldm_x4(uint32_t* r, uint32_t addr) {
    asm volatile("ldmatrix.sync.aligned.m8n8.x4.shared.b16 {%0,%1,%2,%3}, [%4];"
        : "=r"(r[0]), "=r"(r[1]), "=r"(r[2]), "=r"(r[3]) : "r"(addr));
}
__device__ __forceinline__ void mma_bf16(float* d, const uint32_t* a,
                                         uint32_t b0, uint32_t b1) {
    asm volatile("mma.sync.aligned.m16n8k16.row.col.f32.bf16.bf16.f32 "
        "{%0,%1,%2,%3}, {%4,%5,%6,%7}, {%8,%9}, {%0,%1,%2,%3};"
        : "+f"(d[0]), "+f"(d[1]), "+f"(d[2]), "+f"(d[3])
        : "r"(a[0]), "r"(a[1]), "r"(a[2]), "r"(a[3]), "r"(b0), "r"(b1));
}

// ---------------- prep: weight split + bias concat (stream A) ----------------
__global__ void prep_all(
    const float* __restrict__ inpw,
    const float* __restrict__ l0wl, const float* __restrict__ l0wr,
    const float* __restrict__ l1wl, const float* __restrict__ l1wr,
    const float* __restrict__ l2wl, const float* __restrict__ l2wr,
    const float* __restrict__ resw,
    const float* __restrict__ inpb,
    const float* __restrict__ l0bl, const float* __restrict__ l0br,
    const float* __restrict__ l1bl, const float* __restrict__ l1br,
    const float* __restrict__ l2bl, const float* __restrict__ l2br)
{
    int idx = blockIdx.x * blockDim.x + threadIdx.x;
    if (idx < WTOT) {
        float v;
        if (idx < W1OFF) {                       // W0: 1152 x 128
            int ng = idx >> 7, k = idx & 127;
            int sub = ng / 384, nl = ng - sub * 384;
            const float* w = (sub == 0) ? inpw : (sub == 1) ? l0wl : l0wr;
            v = w[k * 384 + nl];
        } else if (idx < W2OFF) {                // W1: 768 x 384
            int rem = idx - W1OFF;
            int ng = rem / 384, k = rem - ng * 384;
            const float* w = (ng < 384) ? l1wl : l1wr;
            int nl = (ng < 384) ? ng : ng - 384;
            v = w[k * 384 + nl];
        } else {                                 // W2: 256 x 384 (pad >=192)
            int rem = idx - W2OFF;
            int ng = rem / 384, k = rem - ng * 384;
            if      (ng < 64)  v = l2wl[k * 64 + ng];
            else if (ng < 128) v = l2wr[k * 64 + ng - 64];
            else if (ng < 192) v = resw[k * 64 + ng - 128];
            else               v = 0.f;
        }
        __nv_bfloat16 hi = __float2bfloat16(v);
        g_wh[idx] = hi;
        g_wl[idx] = __float2bfloat16(v - __bfloat162float(hi));
        return;
    }
    int r = idx - WTOT;
    if (r < BTOT) {
        float v = 0.f;
        if      (r < 384)  v = inpb[r];
        else if (r < 768)  v = l0bl[r - 384];
        else if (r < 1152) v = l0br[r - 768];
        else if (r < 1536) v = l1bl[r - 1152];
        else if (r < 1920) v = l1br[r - 1536];
        else if (r < 1984) v = l2bl[r - 1920];
        else if (r < 2048) v = l2br[r - 1984];
        g_biascat[r] = v;
    }
}
#define PREP_TOT (WTOT + BTOT)

// ---------------- CSR build + clears (stream B) ----------------
__global__ void clearB() {     // deg + pool + esrc pad
    int i = blockIdx.x * blockDim.x + threadIdx.x;
    if (i < Nn) g_deg[i] = 0;
    if (i < NGg * Cc) g_pool[i] = 0.f;
    if (i < 8) g_esrc[EA + i] = 0;
}

__global__ void csr_count(const int* __restrict__ ei) {
    int e = blockIdx.x * blockDim.x + threadIdx.x;
    if (e >= EA) return;
    int d = (e < Ee) ? ei[Ee + e] : (e - Ee);
    atomicAdd(&g_deg[d], 1);
}

__global__ void csr_scan() {
    __shared__ int part[1024];
    const int per = (Nn + 1023) / 1024;
    int t = threadIdx.x;
    int s = 0;
    #pragma unroll
    for (int k = 0; k < per; ++k) { int i = t * per + k; if (i < Nn) s += g_deg[i]; }
    part[t] = s;
    __syncthreads();
    for (int off = 1; off < 1024; off <<= 1) {
        int v = (t >= off) ? part[t - off] : 0;
        __syncthreads();
        part[t] += v;
        __syncthreads();
    }
    int run = part[t] - s;
    #pragma unroll
    for (int k = 0; k < per; ++k) {
        int i = t * per + k;
        if (i < Nn) { g_indptr[i] = run; g_cursor[i] = run; run += g_deg[i]; }
    }
    if (t == 0) g_indptr[Nn] = EA;
}

__global__ void csr_scatter(const int* __restrict__ ei) {
    int e = blockIdx.x * blockDim.x + threadIdx.x;
    if (e >= EA) return;
    int s, d;
    if (e < Ee) { s = ei[e]; d = ei[Ee + e]; }
    else        { s = d = e - Ee; }
    int pos = atomicAdd(&g_cursor[d], 1);
    g_esrc[pos] = s;
}

// fp32 -> (hi, lo) bf16 split (layer-0 input only; runs on stream B)
__global__ void conv_hilo(const float* __restrict__ src, int n4) {
    int i = blockIdx.x * blockDim.x + threadIdx.x;
    if (i >= n4) return;
    float4 v = reinterpret_cast<const float4*>(src)[i];
    __nv_bfloat16 h0 = __float2bfloat16(v.x), h1 = __float2bfloat16(v.y);
    __nv_bfloat16 h2 = __float2bfloat16(v.z), h3 = __float2bfloat16(v.w);
    g_ah[i * 4 + 0] = h0; g_ah[i * 4 + 1] = h1;
    g_ah[i * 4 + 2] = h2; g_ah[i * 4 + 3] = h3;
    g_al[i * 4 + 0] = __float2bfloat16(v.x - __bfloat162float(h0));
    g_al[i * 4 + 1] = __float2bfloat16(v.y - __bfloat162float(h1));
    g_al[i * 4 + 2] = __float2bfloat16(v.z - __bfloat162float(h2));
    g_al[i * 4 + 3] = __float2bfloat16(v.w - __bfloat162float(h3));
}

// ---------------- HMMA split-bf16 GEMM, 4-buffer single-K-pass ----------------
// Columns in [hcol0, hcol0+hcolw) -> fp16 hout (ld=hld); others -> fp32 out (ld=ldout).
#define PADK 40
#define TILEB (128 * PADK * 2)     // 10240 bytes per tile
#define STAGEB (4 * TILEB)         // 40960 bytes per stage
#define SMEM_MM (2 * STAGEB)       // 81920

__global__ __launch_bounds__(256, 2) void mm_mma(
    const __nv_bfloat16* __restrict__ Ah, const __nv_bfloat16* __restrict__ Al,
    const __nv_bfloat16* __restrict__ Bh, const __nv_bfloat16* __restrict__ Bl,
    const float* __restrict__ bias, float* __restrict__ out,
    __half* __restrict__ hout, int hld, int hcol0, int hcolw,
    int K, int ldout)
{
    extern __shared__ __align__(16) char dsm[];
    uint32_t sbase = smem_u32(dsm);
    int tid = threadIdx.x, wid = tid >> 5, lane = tid & 31;
    int m0 = blockIdx.y * 128, n0 = blockIdx.x * 128;
    int warp_m = wid & 3, warp_n = wid >> 2;
    int nk = K >> 5;

    auto load_chunk = [&](int stage, int k0) {
        uint32_t dst0 = sbase + stage * STAGEB;
        #pragma unroll
        for (int it = 0; it < 8; ++it) {
            int idx = tid + it * 256;
            int buf = idx >> 9;
            int w   = idx & 511;
            int r   = w >> 2, q = w & 3;
            const __nv_bfloat16* src;
            if      (buf == 0) src = Ah + (size_t)(m0 + r) * K + k0 + q * 8;
            else if (buf == 1) src = Al + (size_t)(m0 + r) * K + k0 + q * 8;
            else if (buf == 2) src = Bh + (size_t)(n0 + r) * K + k0 + q * 8;
            else               src = Bl + (size_t)(n0 + r) * K + k0 + q * 8;
            CPASY16(dst0 + buf * TILEB + (r * PADK + q * 8) * 2, src);
        }
        CPASY_COMMIT();
    };

    load_chunk(0, 0);

    float acc[2][8][4];
    #pragma unroll
    for (int mi = 0; mi < 2; ++mi)
        #pragma unroll
        for (int nt = 0; nt < 8; ++nt)
            #pragma unroll
            for (int q = 0; q < 4; ++q) acc[mi][nt][q] = 0.f;

    int gA = lane >> 3, lrA = lane & 7;

    for (int c = 0; c < nk; ++c) {
        int s = c & 1;
        if (c + 1 < nk) { load_chunk(s ^ 1, (c + 1) << 5); CPASY_WAIT1(); }
        else            { CPASY_WAIT0(); }
        __syncthreads();

        uint32_t st = sbase + s * STAGEB;
        uint32_t aH = st + (warp_m * 32) * PADK * 2;
        uint32_t aL = st + TILEB + (warp_m * 32) * PADK * 2;
        uint32_t bH = st + 2 * TILEB + (warp_n * 64) * PADK * 2;
        uint32_t bL = st + 3 * TILEB + (warp_n * 64) * PADK * 2;

        #pragma unroll
        for (int kk = 0; kk < 32; kk += 16) {
            uint32_t afrH[2][4], afrL[2][4];
            #pragma unroll
            for (int mi = 0; mi < 2; ++mi) {
                int row = mi * 16 + ((gA & 1) << 3) + lrA;
                int col = ((gA >> 1) << 3) + kk;
                ldm_x4(afrH[mi], aH + (row * PADK + col) * 2);
                ldm_x4(afrL[mi], aL + (row * PADK + col) * 2);
            }
            uint32_t bfr[4][4];
            #pragma unroll
            for (int nb = 0; nb < 4; ++nb) {
                int n = nb * 16 + ((gA >> 1) << 3) + lrA;
                int col = ((gA & 1) << 3) + kk;
                ldm_x4(bfr[nb], bH + (n * PADK + col) * 2);
            }
            #pragma unroll
            for (int mi = 0; mi < 2; ++mi)
                #pragma unroll
                for (int nt = 0; nt < 8; ++nt) {
                    mma_bf16(acc[mi][nt], afrH[mi],
                             bfr[nt >> 1][(nt & 1) * 2], bfr[nt >> 1][(nt & 1) * 2 + 1]);
                    mma_bf16(acc[mi][nt], afrL[mi],
                             bfr[nt >> 1][(nt & 1) * 2], bfr[nt >> 1][(nt & 1) * 2 + 1]);
                }
            #pragma unroll
            for (int nb = 0; nb < 4; ++nb) {
                int n = nb * 16 + ((gA >> 1) << 3) + lrA;
                int col = ((gA & 1) << 3) + kk;
                ldm_x4(bfr[nb], bL + (n * PADK + col) * 2);
            }
            #pragma unroll
            for (int mi = 0; mi < 2; ++mi)
                #pragma unroll
                for (int nt = 0; nt < 8; ++nt)
                    mma_bf16(acc[mi][nt], afrH[mi],
                             bfr[nt >> 1][(nt & 1) * 2], bfr[nt >> 1][(nt & 1) * 2 + 1]);
        }
        __syncthreads();
    }

    int rl = lane >> 2, cl = (lane & 3) * 2;
    #pragma unroll
    for (int mi = 0; mi < 2; ++mi) {
        int r0 = m0 + warp_m * 32 + mi * 16 + rl;
        #pragma unroll
        for (int nt = 0; nt < 8; ++nt) {
            int cb = n0 + warp_n * 64 + nt * 8 + cl;
            float b0 = bias[cb], b1 = bias[cb + 1];
            bool inh = (unsigned)(cb - hcol0) < (unsigned)hcolw;
            int hc = cb - hcol0;
            if (r0 < Nn) {
                float v0 = acc[mi][nt][0] + b0, v1 = acc[mi][nt][1] + b1;
                if (inh)
                    *reinterpret_cast<__half2*>(&hout[(size_t)r0 * hld + hc]) = __floats2half2_rn(v0, v1);
                else {
                    float2 v = { v0, v1 };
                    *reinterpret_cast<float2*>(&out[(size_t)r0 * ldout + cb]) = v;
                }
            }
            if (r0 + 8 < Nn) {
                float v0 = acc[mi][nt][2] + b0, v1 = acc[mi][nt][3] + b1;
                if (inh)
                    *reinterpret_cast<__half2*>(&hout[(size_t)(r0 + 8) * hld + hc]) = __floats2half2_rn(v0, v1);
                else {
                    float2 v = { v0, v1 };
                    *reinterpret_cast<float2*>(&out[(size_t)(r0 + 8) * ldout + cb]) = v;
                }
            }
        }
    }
}

// ---------------- fused GATv2: convergent 2-edge half-warp, all-fp16 inputs ----------------
// Warp per (node, head). xl at hf col 0, xr at uint2 offset offR4 in the same row.
__global__ void gat_fused(
    const __half* __restrict__ xh, int xld4, int offR4,
    const float* __restrict__ att, const float* __restrict__ bias,
    const float* __restrict__ resf, int ldresf,
    const __nv_bfloat16* __restrict__ resh, const __nv_bfloat16* __restrict__ resl, int ldresb,
    float* __restrict__ outf, int ldoutf,
    __nv_bfloat16* __restrict__ outh, __nv_bfloat16* __restrict__ outl,
    const int* __restrict__ pool_batch, int H, int npb)
{
    int wid = threadIdx.x >> 5;
    int lane = threadIdx.x & 31;
    int node = blockIdx.x * npb + wid / H;
    int head = wid - (wid / H) * H;
    if (node >= Nn) return;
    int h = lane >> 4, gl = lane & 15;
    int beg = g_indptr[node], end = g_indptr[node + 1];
    int c0 = head * 64 + gl * 4;
    int coff = head * 16 + gl;

    const uint2* xb = reinterpret_cast<const uint2*>(xh);
    float4 af = *reinterpret_cast<const float4*>(att + c0);
    __half2 ah[2] = { __floats2half2_rn(af.x, af.y), __floats2half2_rn(af.z, af.w) };
    uint2 xr2 = xb[(size_t)node * xld4 + offR4 + coff];      // xr already fp16
    __half2 xrh[2] = { *reinterpret_cast<__half2*>(&xr2.x), *reinterpret_cast<__half2*>(&xr2.y) };
    const __half2 p2 = __floats2half2_rn(0.2f, 0.2f);

    float ssum = 0.f;
    float acc[4] = {};
    uint2 hv_next = xb[(size_t)g_esrc[beg + h] * xld4 + coff];   // esrc padded -> safe

    for (int j = beg; j < end; j += 2) {
        uint2 hv = hv_next;
        hv_next = xb[(size_t)g_esrc[j + 2 + h] * xld4 + coff];
        const __half2* xvh = reinterpret_cast<const __half2*>(&hv);
        __half2 t0 = __hadd2(xvh[0], xrh[0]);
        __half2 t1 = __hadd2(xvh[1], xrh[1]);
        t0 = __hmax2(t0, __hmul2(t0, p2));           // leaky_relu(0.2)
        t1 = __hmax2(t1, __hmul2(t1, p2));
        __half2 dot = __hmul2(ah[0], t0);
        dot = __hfma2(ah[1], t1, dot);
        float p = __low2float(dot) + __high2float(dot);
        p += __shfl_xor_sync(0xffffffffu, p, 1);
        p += __shfl_xor_sync(0xffffffffu, p, 2);
        p += __shfl_xor_sync(0xffffffffu, p, 4);
        p += __shfl_xor_sync(0xffffffffu, p, 8);
        float w = (j + h < end) ? __expf(p) : 0.f;
        ssum += w;
        float2 x0 = __half22float2(xvh[0]);
        float2 x1 = __half22float2(xvh[1]);
        acc[0] = fmaf(w, x0.x, acc[0]);
        acc[1] = fmaf(w, x0.y, acc[1]);
        acc[2] = fmaf(w, x1.x, acc[2]);
        acc[3] = fmaf(w, x1.y, acc[3]);
    }
    ssum += __shfl_xor_sync(0xffffffffu, ssum, 16);
    #pragma unroll
    for (int k = 0; k < 4; ++k)
        acc[k] += __shfl_xor_sync(0xffffffffu, acc[k], 16);
    if (h != 0) return;

    float inv = 1.f / (ssum + 1e-16f);
    float4 bf4 = *reinterpret_cast<const float4*>(bias + c0);
    float bb[4] = { bf4.x, bf4.y, bf4.z, bf4.w };
    float v[4];
    #pragma unroll
    for (int k = 0; k < 4; ++k) {
        float t = acc[k] * inv + bb[k];
        v[k] = (t > 0.f) ? t : (__expf(t) - 1.f);        // ELU
    }
    if (resf) {
        float4 q = *reinterpret_cast<const float4*>(resf + (size_t)node * ldresf + c0);
        v[0] += q.x; v[1] += q.y; v[2] += q.z; v[3] += q.w;
    } else {
        uint2 rhu = *reinterpret_cast<const uint2*>(resh + (size_t)node * ldresb + c0);
        uint2 rlu = *reinterpret_cast<const uint2*>(resl + (size_t)node * ldresb + c0);
        const __nv_bfloat162* rh2 = reinterpret_cast<const __nv_bfloat162*>(&rhu);
        const __nv_bfloat162* rl2 = reinterpret_cast<const __nv_bfloat162*>(&rlu);
        #pragma unroll
        for (int k = 0; k < 2; ++k) {
            float2 fh = __bfloat1622float2(rh2[k]);
            float2 fl = __bfloat1622float2(rl2[k]);
            v[2 * k]     += fh.x + fl.x;
            v[2 * k + 1] += fh.y + fl.y;
        }
    }
    if (outf)
        *reinterpret_cast<float4*>(outf + (size_t)node * ldoutf + c0) =
            make_float4(v[0], v[1], v[2], v[3]);
    if (outh) {
        __nv_bfloat162 hv2[2], lv2[2];
        #pragma unroll
        for (int k = 0; k < 2; ++k) {
            __nv_bfloat16 b0 = __float2bfloat16(v[2 * k]), b1 = __float2bfloat16(v[2 * k + 1]);
            hv2[k].x = b0; hv2[k].y = b1;
            lv2[k].x = __float2bfloat16(v[2 * k] - __bfloat162float(b0));
            lv2[k].y = __float2bfloat16(v[2 * k + 1] - __bfloat162float(b1));
        }
        *reinterpret_cast<uint2*>(outh + (size_t)node * HCc + c0) = *reinterpret_cast<uint2*>(hv2);
        *reinterpret_cast<uint2*>(outl + (size_t)node * HCc + c0) = *reinterpret_cast<uint2*>(lv2);
    }
    if (pool_batch) {                              // fused graph pooling (layer 2)
        int g = pool_batch[node];
        #pragma unroll
        for (int k = 0; k < 4; ++k)
            atomicAdd(&g_pool[g * Cc + c0 + k], v[k]);
    }
}

// ---------------- dense head ----------------
__global__ __launch_bounds__(1024) void dense_head(
    const float* __restrict__ d1w, const float* __restrict__ d1b,
    const float* __restrict__ bng, const float* __restrict__ bnb,
    const float* __restrict__ bnm, const float* __restrict__ bnv,
    const float* __restrict__ d2w, const float* __restrict__ d2b,
    float* __restrict__ z)
{
    __shared__ float sp[NGg * Cc];
    __shared__ float t1[NGg * Cc];
    int tid = threadIdx.x;
    for (int idx = tid; idx < NGg * Cc; idx += 1024) sp[idx] = g_pool[idx];
    __syncthreads();
    for (int idx = tid; idx < NGg * Cc; idx += 1024) {
        int r = idx >> 6, c = idx & 63;
        float s = d1b[c];
        #pragma unroll
        for (int k = 0; k < 64; ++k) s = fmaf(sp[r * 64 + k], d1w[k * 64 + c], s);
        s = (s - bnm[c]) * rsqrtf(bnv[c] + 1e-5f) * bng[c] + bnb[c];
        t1[idx] = (s > 0.f) ? s : 0.f;
    }
    __syncthreads();
    for (int idx = tid; idx < NGg * NCc; idx += 1024) {
        int r = idx >> 4, c = idx & 15;
        float s = d2b[c];
        #pragma unroll
        for (int k = 0; k < 64; ++k) s = fmaf(t1[r * 64 + k], d2w[k * 16 + c], s);
        z[idx] = s;
    }
}

// ---------------- host launcher ----------------
extern "C" void kernel_launch(void* const* d_in, const int* in_sizes, int n_in,
                              void* d_out, int out_size)
{
    const float* x      = (const float*)d_in[0];
    const int*   ei     = (const int*)  d_in[1];
    const int*   batch  = (const int*)  d_in[2];
    const float* inp_w  = (const float*)d_in[3];
    const float* inp_b  = (const float*)d_in[4];
    const float* l0_wl  = (const float*)d_in[5];
    const float* l0_bl  = (const float*)d_in[6];
    const float* l0_wr  = (const float*)d_in[7];
    const float* l0_br  = (const float*)d_in[8];
    const float* l0_att = (const float*)d_in[9];
    const float* l0_bias= (const float*)d_in[10];
    const float* l1_wl  = (const float*)d_in[11];
    const float* l1_bl  = (const float*)d_in[12];
    const float* l1_wr  = (const float*)d_in[13];
    const float* l1_br  = (const float*)d_in[14];
    const float* l1_att = (const float*)d_in[15];
    const float* l1_bias= (const float*)d_in[16];
    const float* l2_wl  = (const float*)d_in[17];
    const float* l2_bl  = (const float*)d_in[18];
    const float* l2_wr  = (const float*)d_in[19];
    const float* l2_br  = (const float*)d_in[20];
    const float* l2_att = (const float*)d_in[21];
    const float* l2_bias= (const float*)d_in[22];
    const float* res_w  = (const float*)d_in[23];
    const float* d1_w   = (const float*)d_in[24];
    const float* d1_b   = (const float*)d_in[25];
    const float* bn_g   = (const float*)d_in[26];
    const float* bn_b   = (const float*)d_in[27];
    const float* bn_m   = (const float*)d_in[28];
    const float* bn_v   = (const float*)d_in[29];
    const float* d2_w   = (const float*)d_in[30];
    const float* d2_b   = (const float*)d_in[31];
    float* out = (float*)d_out;

    float *p_big, *p_bias;
    __nv_bfloat16 *p_ah, *p_al, *p_wh, *p_wl;
    __half *p_hf;
    cudaGetSymbolAddress((void**)&p_big,  g_big);
    cudaGetSymbolAddress((void**)&p_ah,   g_ah);
    cudaGetSymbolAddress((void**)&p_al,   g_al);
    cudaGetSymbolAddress((void**)&p_wh,   g_wh);
    cudaGetSymbolAddress((void**)&p_wl,   g_wl);
    cudaGetSymbolAddress((void**)&p_hf,   g_hf);
    cudaGetSymbolAddress((void**)&p_bias, g_biascat);

    cudaFuncSetAttribute(mm_mma, cudaFuncAttributeMaxDynamicSharedMemorySize, SMEM_MM);

    // fork conv + CSR chain onto side stream (capture-legal fork/join)
    cudaStream_t sB;
    cudaStreamCreateWithFlags(&sB, cudaStreamNonBlocking);
    cudaEvent_t evFork, evConv, evJoin;
    cudaEventCreateWithFlags(&evFork, cudaEventDisableTiming);
    cudaEventCreateWithFlags(&evConv, cudaEventDisableTiming);
    cudaEventCreateWithFlags(&evJoin, cudaEventDisableTiming);

    cudaEventRecord(evFork, 0);
    cudaStreamWaitEvent(sB, evFork, 0);
    conv_hilo<<<(Nn * 128 / 4 + 255) / 256, 256, 0, sB>>>(x, Nn * 128 / 4);
    cudaEventRecord(evConv, sB);
    clearB<<<(Nn + 255) / 256, 256, 0, sB>>>();
    csr_count<<<(EA + 255) / 256, 256, 0, sB>>>(ei);
    csr_scan<<<1, 1024, 0, sB>>>();
    csr_scatter<<<(EA + 255) / 256, 256, 0, sB>>>(ei);
    cudaEventRecord(evJoin, sB);

    // stream A: weight prep (concurrent with conv+CSR)
    prep_all<<<(PREP_TOT + 255) / 256, 256>>>(
        inp_w, l0_wl, l0_wr, l1_wl, l1_wr, l2_wl, l2_wr, res_w,
        inp_b, l0_bl, l0_br, l1_bl, l1_br, l2_bl, l2_br);

    const int MB = 157;  // ceil(20000/128)

    // ---- layer 0: [x_res(fp32,384) | xl | xr (fp16,768)], K=128 ----
    cudaStreamWaitEvent(0, evConv, 0);   // ah/al ready
    mm_mma<<<dim3(9, MB), 256, SMEM_MM>>>(p_ah, p_al, p_wh + W0OFF, p_wl + W0OFF,
                                          p_bias + B0OFF, p_big,
                                          p_hf, 768, 384, 768, 128, 384);
    cudaStreamWaitEvent(0, evJoin, 0);   // CSR ready before first gat
    gat_fused<<<Nn, 32 * Hh>>>(p_hf, 192, 96, l0_att, l0_bias,
                               p_big, 384, nullptr, nullptr, 0,
                               nullptr, 0, p_ah, p_al, nullptr, Hh, 1);   // h0 -> ah/al

    // ---- layer 1: [xl | xr] all fp16 (768), K=384 ----
    mm_mma<<<dim3(6, MB), 256, SMEM_MM>>>(p_ah, p_al, p_wh + W1OFF, p_wl + W1OFF,
                                          p_bias + B1OFF, p_big,
                                          p_hf, 768, 0, 768, 384, 384);
    gat_fused<<<Nn, 32 * Hh>>>(p_hf, 192, 96, l1_att, l1_bias,
                               nullptr, 0, p_ah, p_al, HCc,
                               nullptr, 0, p_ah, p_al, nullptr, Hh, 1);   // res=h0, h1 -> ah/al

    // ---- layer 2: [xl | xr (fp16,128) | res_proj (fp32 at col 128)], K=384 ----
    mm_mma<<<dim3(2, MB), 256, SMEM_MM>>>(p_ah, p_al, p_wh + W2OFF, p_wl + W2OFF,
                                          p_bias + B2OFF, p_big - 128,   // fp32 writes at cb>=128 -> col 0
                                          p_hf, 128, 0, 128, 384, 384);
    gat_fused<<<(Nn + 7) / 8, 256>>>(p_hf, 32, 16, l2_att, l2_bias,
                                     p_big, 384, nullptr, nullptr, 0,
                                     out, 64, nullptr, nullptr, batch, 1, 8);  // h -> d_out, fused pool

    dense_head<<<1, 1024>>>(d1_w, d1_b, bn_g, bn_b, bn_m, bn_v, d2_w, d2_b,
                            out + (size_t)Nn * Cc);

    cudaEventDestroy(evFork);
    cudaEventDestroy(evConv);
    cudaEventDestroy(evJoin);
    cudaStreamDestroy(sB);
}

// round 15
// speedup vs baseline: 1.2991x; 1.1265x over previous
#include <cuda_runtime.h>
#include <cuda_bf16.h>
#include <cuda_fp16.h>
#include <cstdint>
#include <math.h>

// Problem constants
#define Nn    20000
#define Mpad  20096            // 157 * 128
#define Ee    320000
#define EA    (Ee + Nn)
#define INF_  128
#define Hh    6
#define Cc    64
#define HCc   384
#define NGg   64
#define NCc   16

// weight-prep element offsets in concatenated [N x K] K-major bf16 buffers
#define W0OFF 0                // layer0: 1152 x 128
#define W1OFF 147456           // layer1: 768 x 384
#define W2OFF 442368           // layer2: 256 x 384 (rows 192..255 zero pad)
#define WTOT  540672
#define B0OFF 0
#define B1OFF 1152
#define B2OFF 1920
#define BTOT  2176

// ---------------- device scratch ----------------
__device__ __align__(16) __nv_bfloat16 g_ah[(size_t)Mpad * HCc];
__device__ __align__(16) __nv_bfloat16 g_al[(size_t)Mpad * HCc];
__device__ __align__(16) __half        g_hf[(size_t)Mpad * 768];  // fp16 [xl|xr] copy
__device__ __align__(16) __half        g_gh[(size_t)Mpad * HCc];  // fp16 h0 (L1 GEMM A)
__device__ __align__(16) __nv_bfloat16 g_wh[WTOT];
__device__ __align__(16) __nv_bfloat16 g_wl[WTOT];
__device__ __align__(16) __half        g_whf[768 * 384];          // fp16 W1
__device__ float g_biascat[BTOT];
__device__ float g_big[(size_t)Mpad * 384];    // fp32 region (x_res / res_proj only)
__device__ int   g_deg[Nn + 1];
__device__ int   g_indptr[Nn + 1];
__device__ int   g_cursor[Nn];
__device__ int   g_esrc[EA + 8];               // src node per CSR slot (+8 pad)
__device__ float g_pool[NGg * Cc];

// ---------------- PTX helpers (plain sm_80+ features only) ----------------
__device__ __forceinline__ uint32_t smem_u32(const void* p) {
    uint32_t a;
    asm("{ .reg .u64 t; cvta.to.shared.u64 t, %1; cvt.u32.u64 %0, t; }" : "=r"(a) : "l"(p));
    return a;
}
#define CPASY16(dst, src) asm volatile("cp.async.cg.shared.global [%0], [%1], 16;" :: "r"(dst), "l"(src))
#define CPASY_COMMIT()    asm volatile("cp.async.commit_group;" ::: "memory")
#define CPASY_WAIT1()     asm volatile("cp.async.wait_group 1;" ::: "memory")
#define CPASY_WAIT0()     asm volatile("cp.async.wait_group 0;" ::: "memory")

__device__ __forceinline__ void ldm_x4(uint32_t* r, uint32_t addr) {
    asm volatile("ldmatrix.sync.aligned.m8n8.x4.shared.b16 {%0,%1,%2,%3}, [%4];"
        : "=r"(r[0]), "=r"(r[1]), "=r"(r[2]), "=r"(r[3]) : "r"(addr));
}
__device__ __forceinline__ void mma_bf16(float* d, const uint32_t* a,
                                         uint32_t b0, uint32_t b1) {
    asm volatile("mma.sync.aligned.m16n8k16.row.col.f32.bf16.bf16.f32 "
        "{%0,%1,%2,%3}, {%4,%5,%6,%7}, {%8,%9}, {%0,%1,%2,%3};"
        : "+f"(d[0]), "+f"(d[1]), "+f"(d[2]), "+f"(d[3])
        : "r"(a[0]), "r"(a[1]), "r"(a[2]), "r"(a[3]), "r"(b0), "r"(b1));
}
__device__ __forceinline__ void mma_fp16(float* d, const uint32_t* a,
                                         uint32_t b0, uint32_t b1) {
    asm volatile("mma.sync.aligned.m16n8k16.row.col.f32.f16.f16.f32 "
        "{%0,%1,%2,%3}, {%4,%5,%6,%7}, {%8,%9}, {%0,%1,%2,%3};"
        : "+f"(d[0]), "+f"(d[1]), "+f"(d[2]), "+f"(d[3])
        : "r"(a[0]), "r"(a[1]), "r"(a[2]), "r"(a[3]), "r"(b0), "r"(b1));
}

// ---------------- prep: weight split + bias concat (stream A) ----------------
__global__ void prep_all(
    const float* __restrict__ inpw,
    const float* __restrict__ l0wl, const float* __restrict__ l0wr,
    const float* __restrict__ l1wl, const float* __restrict__ l1wr,
    const float* __restrict__ l2wl, const float* __restrict__ l2wr,
    const float* __restrict__ resw,
    const float* __restrict__ inpb,
    const float* __restrict__ l0bl, const float* __restrict__ l0br,
    const float* __restrict__ l1bl, const float* __restrict__ l1br,
    const float* __restrict__ l2bl, const float* __restrict__ l2br)
{
    int idx = blockIdx.x * blockDim.x + threadIdx.x;
    if (idx < WTOT) {
        float v;
        if (idx < W1OFF) {                       // W0: 1152 x 128
            int ng = idx >> 7, k = idx & 127;
            int sub = ng / 384, nl = ng - sub * 384;
            const float* w = (sub == 0) ? inpw : (sub == 1) ? l0wl : l0wr;
            v = w[k * 384 + nl];
        } else if (idx < W2OFF) {                // W1: 768 x 384 (also fp16 copy)
            int rem = idx - W1OFF;
            int ng = rem / 384, k = rem - ng * 384;
            const float* w = (ng < 384) ? l1wl : l1wr;
            int nl = (ng < 384) ? ng : ng - 384;
            v = w[k * 384 + nl];
            g_whf[rem] = __float2half(v);
        } else {                                 // W2: 256 x 384 (pad >=192)
            int rem = idx - W2OFF;
            int ng = rem / 384, k = rem - ng * 384;
            if      (ng < 64)  v = l2wl[k * 64 + ng];
            else if (ng < 128) v = l2wr[k * 64 + ng - 64];
            else if (ng < 192) v = resw[k * 64 + ng - 128];
            else               v = 0.f;
        }
        __nv_bfloat16 hi = __float2bfloat16(v);
        g_wh[idx] = hi;
        g_wl[idx] = __float2bfloat16(v - __bfloat162float(hi));
        return;
    }
    int r = idx - WTOT;
    if (r < BTOT) {
        float v = 0.f;
        if      (r < 384)  v = inpb[r];
        else if (r < 768)  v = l0bl[r - 384];
        else if (r < 1152) v = l0br[r - 768];
        else if (r < 1536) v = l1bl[r - 1152];
        else if (r < 1920) v = l1br[r - 1536];
        else if (r < 1984) v = l2bl[r - 1920];
        else if (r < 2048) v = l2br[r - 1984];
        g_biascat[r] = v;
    }
}
#define PREP_TOT (WTOT + BTOT)

// ---------------- CSR build + clears (stream B) ----------------
__global__ void clearB() {     // deg + pool + esrc pad
    int i = blockIdx.x * blockDim.x + threadIdx.x;
    if (i < Nn) g_deg[i] = 0;
    if (i < NGg * Cc) g_pool[i] = 0.f;
    if (i < 8) g_esrc[EA + i] = 0;
}

__global__ void csr_count(const int* __restrict__ ei) {
    int e = blockIdx.x * blockDim.x + threadIdx.x;
    if (e >= EA) return;
    int d = (e < Ee) ? ei[Ee + e] : (e - Ee);
    atomicAdd(&g_deg[d], 1);
}

__global__ void csr_scan() {
    __shared__ int part[1024];
    const int per = (Nn + 1023) / 1024;
    int t = threadIdx.x;
    int s = 0;
    #pragma unroll
    for (int k = 0; k < per; ++k) { int i = t * per + k; if (i < Nn) s += g_deg[i]; }
    part[t] = s;
    __syncthreads();
    for (int off = 1; off < 1024; off <<= 1) {
        int v = (t >= off) ? part[t - off] : 0;
        __syncthreads();
        part[t] += v;
        __syncthreads();
    }
    int run = part[t] - s;
    #pragma unroll
    for (int k = 0; k < per; ++k) {
        int i = t * per + k;
        if (i < Nn) { g_indptr[i] = run; g_cursor[i] = run; run += g_deg[i]; }
    }
    if (t == 0) g_indptr[Nn] = EA;
}

__global__ void csr_scatter(const int* __restrict__ ei) {
    int e = blockIdx.x * blockDim.x + threadIdx.x;
    if (e >= EA) return;
    int s, d;
    if (e < Ee) { s = ei[e]; d = ei[Ee + e]; }
    else        { s = d = e - Ee; }
    int pos = atomicAdd(&g_cursor[d], 1);
    g_esrc[pos] = s;
}

// fp32 -> (hi, lo) bf16 split (layer-0 input only; runs on stream B)
__global__ void conv_hilo(const float* __restrict__ src, int n4) {
    int i = blockIdx.x * blockDim.x + threadIdx.x;
    if (i >= n4) return;
    float4 v = reinterpret_cast<const float4*>(src)[i];
    __nv_bfloat16 h0 = __float2bfloat16(v.x), h1 = __float2bfloat16(v.y);
    __nv_bfloat16 h2 = __float2bfloat16(v.z), h3 = __float2bfloat16(v.w);
    g_ah[i * 4 + 0] = h0; g_ah[i * 4 + 1] = h1;
    g_ah[i * 4 + 2] = h2; g_ah[i * 4 + 3] = h3;
    g_al[i * 4 + 0] = __float2bfloat16(v.x - __bfloat162float(h0));
    g_al[i * 4 + 1] = __float2bfloat16(v.y - __bfloat162float(h1));
    g_al[i * 4 + 2] = __float2bfloat16(v.z - __bfloat162float(h2));
    g_al[i * 4 + 3] = __float2bfloat16(v.w - __bfloat162float(h3));
}

// ---------------- HMMA split-bf16 GEMM, 4-buffer single-K-pass ----------------
#define PADK 40
#define TILEB (128 * PADK * 2)     // 10240 bytes per tile
#define STAGEB (4 * TILEB)         // 40960 bytes per stage
#define SMEM_MM (2 * STAGEB)       // 81920
#define STAGEB_H (2 * TILEB)       // 20480
#define SMEM_MH (2 * STAGEB_H)     // 40960

__global__ __launch_bounds__(256, 2) void mm_mma(
    const __nv_bfloat16* __restrict__ Ah, const __nv_bfloat16* __restrict__ Al,
    const __nv_bfloat16* __restrict__ Bh, const __nv_bfloat16* __restrict__ Bl,
    const float* __restrict__ bias, float* __restrict__ out,
    __half* __restrict__ hout, int hld, int hcol0, int hcolw,
    int K, int ldout)
{
    extern __shared__ __align__(16) char dsm[];
    uint32_t sbase = smem_u32(dsm);
    int tid = threadIdx.x, wid = tid >> 5, lane = tid & 31;
    int m0 = blockIdx.y * 128, n0 = blockIdx.x * 128;
    int warp_m = wid & 3, warp_n = wid >> 2;
    int nk = K >> 5;

    auto load_chunk = [&](int stage, int k0) {
        uint32_t dst0 = sbase + stage * STAGEB;
        #pragma unroll
        for (int it = 0; it < 8; ++it) {
            int idx = tid + it * 256;
            int buf = idx >> 9;
            int w   = idx & 511;
            int r   = w >> 2, q = w & 3;
            const __nv_bfloat16* src;
            if      (buf == 0) src = Ah + (size_t)(m0 + r) * K + k0 + q * 8;
            else if (buf == 1) src = Al + (size_t)(m0 + r) * K + k0 + q * 8;
            else if (buf == 2) src = Bh + (size_t)(n0 + r) * K + k0 + q * 8;
            else               src = Bl + (size_t)(n0 + r) * K + k0 + q * 8;
            CPASY16(dst0 + buf * TILEB + (r * PADK + q * 8) * 2, src);
        }
        CPASY_COMMIT();
    };

    load_chunk(0, 0);

    float acc[2][8][4];
    #pragma unroll
    for (int mi = 0; mi < 2; ++mi)
        #pragma unroll
        for (int nt = 0; nt < 8; ++nt)
            #pragma unroll
            for (int q = 0; q < 4; ++q) acc[mi][nt][q] = 0.f;

    int gA = lane >> 3, lrA = lane & 7;

    for (int c = 0; c < nk; ++c) {
        int s = c & 1;
        if (c + 1 < nk) { load_chunk(s ^ 1, (c + 1) << 5); CPASY_WAIT1(); }
        else            { CPASY_WAIT0(); }
        __syncthreads();

        uint32_t st = sbase + s * STAGEB;
        uint32_t aH = st + (warp_m * 32) * PADK * 2;
        uint32_t aL = st + TILEB + (warp_m * 32) * PADK * 2;
        uint32_t bH = st + 2 * TILEB + (warp_n * 64) * PADK * 2;
        uint32_t bL = st + 3 * TILEB + (warp_n * 64) * PADK * 2;

        #pragma unroll
        for (int kk = 0; kk < 32; kk += 16) {
            uint32_t afrH[2][4], afrL[2][4];
            #pragma unroll
            for (int mi = 0; mi < 2; ++mi) {
                int row = mi * 16 + ((gA & 1) << 3) + lrA;
                int col = ((gA >> 1) << 3) + kk;
                ldm_x4(afrH[mi], aH + (row * PADK + col) * 2);
                ldm_x4(afrL[mi], aL + (row * PADK + col) * 2);
            }
            uint32_t bfr[4][4];
            #pragma unroll
            for (int nb = 0; nb < 4; ++nb) {
                int n = nb * 16 + ((gA >> 1) << 3) + lrA;
                int col = ((gA & 1) << 3) + kk;
                ldm_x4(bfr[nb], bH + (n * PADK + col) * 2);
            }
            #pragma unroll
            for (int mi = 0; mi < 2; ++mi)
                #pragma unroll
                for (int nt = 0; nt < 8; ++nt) {
                    mma_bf16(acc[mi][nt], afrH[mi],
                             bfr[nt >> 1][(nt & 1) * 2], bfr[nt >> 1][(nt & 1) * 2 + 1]);
                    mma_bf16(acc[mi][nt], afrL[mi],
                             bfr[nt >> 1][(nt & 1) * 2], bfr[nt >> 1][(nt & 1) * 2 + 1]);
                }
            #pragma unroll
            for (int nb = 0; nb < 4; ++nb) {
                int n = nb * 16 + ((gA >> 1) << 3) + lrA;
                int col = ((gA & 1) << 3) + kk;
                ldm_x4(bfr[nb], bL + (n * PADK + col) * 2);
            }
            #pragma unroll
            for (int mi = 0; mi < 2; ++mi)
                #pragma unroll
                for (int nt = 0; nt < 8; ++nt)
                    mma_bf16(acc[mi][nt], afrH[mi],
                             bfr[nt >> 1][(nt & 1) * 2], bfr[nt >> 1][(nt & 1) * 2 + 1]);
        }
        __syncthreads();
    }

    int rl = lane >> 2, cl = (lane & 3) * 2;
    #pragma unroll
    for (int mi = 0; mi < 2; ++mi) {
        int r0 = m0 + warp_m * 32 + mi * 16 + rl;
        #pragma unroll
        for (int nt = 0; nt < 8; ++nt) {
            int cb = n0 + warp_n * 64 + nt * 8 + cl;
            float b0 = bias[cb], b1 = bias[cb + 1];
            bool inh = (unsigned)(cb - hcol0) < (unsigned)hcolw;
            int hc = cb - hcol0;
            if (r0 < Nn) {
                float v0 = acc[mi][nt][0] + b0, v1 = acc[mi][nt][1] + b1;
                if (inh)
                    *reinterpret_cast<__half2*>(&hout[(size_t)r0 * hld + hc]) = __floats2half2_rn(v0, v1);
                else {
                    float2 v = { v0, v1 };
                    *reinterpret_cast<float2*>(&out[(size_t)r0 * ldout + cb]) = v;
                }
            }
            if (r0 + 8 < Nn) {
                float v0 = acc[mi][nt][2] + b0, v1 = acc[mi][nt][3] + b1;
                if (inh)
                    *reinterpret_cast<__half2*>(&hout[(size_t)(r0 + 8) * hld + hc]) = __floats2half2_rn(v0, v1);
                else {
                    float2 v = { v0, v1 };
                    *reinterpret_cast<float2*>(&out[(size_t)(r0 + 8) * ldout + cb]) = v;
                }
            }
        }
    }
}

// ---------------- HMMA fp16 1-term GEMM (layer 1), 2-buffer ----------------
__global__ __launch_bounds__(256, 2) void mm_mma_h(
    const __half* __restrict__ A, const __half* __restrict__ B,
    const float* __restrict__ bias, __half* __restrict__ out,
    int K, int ldout)
{
    extern __shared__ __align__(16) char dsm[];
    uint32_t sbase = smem_u32(dsm);
    int tid = threadIdx.x, wid = tid >> 5, lane = tid & 31;
    int m0 = blockIdx.y * 128, n0 = blockIdx.x * 128;
    int warp_m = wid & 3, warp_n = wid >> 2;
    int nk = K >> 5;

    auto load_chunk = [&](int stage, int k0) {
        uint32_t dst0 = sbase + stage * STAGEB_H;
        #pragma unroll
        for (int it = 0; it < 4; ++it) {
            int idx = tid + it * 256;       // 0..1023
            int buf = idx >> 9;             // 0=A, 1=B
            int w   = idx & 511;
            int r   = w >> 2, q = w & 3;
            const __half* src = (buf == 0)
                ? A + (size_t)(m0 + r) * K + k0 + q * 8
                : B + (size_t)(n0 + r) * K + k0 + q * 8;
            CPASY16(dst0 + buf * TILEB + (r * PADK + q * 8) * 2, src);
        }
        CPASY_COMMIT();
    };

    load_chunk(0, 0);

    float acc[2][8][4];
    #pragma unroll
    for (int mi = 0; mi < 2; ++mi)
        #pragma unroll
        for (int nt = 0; nt < 8; ++nt)
            #pragma unroll
            for (int q = 0; q < 4; ++q) acc[mi][nt][q] = 0.f;

    int gA = lane >> 3, lrA = lane & 7;

    for (int c = 0; c < nk; ++c) {
        int s = c & 1;
        if (c + 1 < nk) { load_chunk(s ^ 1, (c + 1) << 5); CPASY_WAIT1(); }
        else            { CPASY_WAIT0(); }
        __syncthreads();

        uint32_t st = sbase + s * STAGEB_H;
        uint32_t aT = st + (warp_m * 32) * PADK * 2;
        uint32_t bT = st + TILEB + (warp_n * 64) * PADK * 2;

        #pragma unroll
        for (int kk = 0; kk < 32; kk += 16) {
            uint32_t afr[2][4];
            #pragma unroll
            for (int mi = 0; mi < 2; ++mi) {
                int row = mi * 16 + ((gA & 1) << 3) + lrA;
                int col = ((gA >> 1) << 3) + kk;
                ldm_x4(afr[mi], aT + (row * PADK + col) * 2);
            }
            uint32_t bfr[4][4];
            #pragma unroll
            for (int nb = 0; nb < 4; ++nb) {
                int n = nb * 16 + ((gA >> 1) << 3) + lrA;
                int col = ((gA & 1) << 3) + kk;
                ldm_x4(bfr[nb], bT + (n * PADK + col) * 2);
            }
            #pragma unroll
            for (int mi = 0; mi < 2; ++mi)
                #pragma unroll
                for (int nt = 0; nt < 8; ++nt)
                    mma_fp16(acc[mi][nt], afr[mi],
                             bfr[nt >> 1][(nt & 1) * 2], bfr[nt >> 1][(nt & 1) * 2 + 1]);
        }
        __syncthreads();
    }

    int rl = lane >> 2, cl = (lane & 3) * 2;
    #pragma unroll
    for (int mi = 0; mi < 2; ++mi) {
        int r0 = m0 + warp_m * 32 + mi * 16 + rl;
        #pragma unroll
        for (int nt = 0; nt < 8; ++nt) {
            int cb = n0 + warp_n * 64 + nt * 8 + cl;
            float b0 = bias[cb], b1 = bias[cb + 1];
            if (r0 < Nn)
                *reinterpret_cast<__half2*>(&out[(size_t)r0 * ldout + cb]) =
                    __floats2half2_rn(acc[mi][nt][0] + b0, acc[mi][nt][1] + b1);
            if (r0 + 8 < Nn)
                *reinterpret_cast<__half2*>(&out[(size_t)(r0 + 8) * ldout + cb]) =
                    __floats2half2_rn(acc[mi][nt][2] + b0, acc[mi][nt][3] + b1);
        }
    }
}

// ---------------- fused GATv2: convergent 2-edge half-warp, all-fp16 inputs ----------------
__global__ void gat_fused(
    const __half* __restrict__ xh, int xld4, int offR4,
    const float* __restrict__ att, const float* __restrict__ bias,
    const float* __restrict__ resf, int ldresf,
    const __nv_bfloat16* __restrict__ resh, const __nv_bfloat16* __restrict__ resl, int ldresb,
    float* __restrict__ outf, int ldoutf,
    __nv_bfloat16* __restrict__ outh, __nv_bfloat16* __restrict__ outl,
    __half* __restrict__ outg,
    const int* __restrict__ pool_batch, int H, int npb)
{
    int wid = threadIdx.x >> 5;
    int lane = threadIdx.x & 31;
    int node = blockIdx.x * npb + wid / H;
    int head = wid - (wid / H) * H;
    if (node >= Nn) return;
    int h = lane >> 4, gl = lane & 15;
    int beg = g_indptr[node], end = g_indptr[node + 1];
    int c0 = head * 64 + gl * 4;
    int coff = head * 16 + gl;

    const uint2* xb = reinterpret_cast<const uint2*>(xh);
    float4 af = *reinterpret_cast<const float4*>(att + c0);
    __half2 ah[2] = { __floats2half2_rn(af.x, af.y), __floats2half2_rn(af.z, af.w) };
    uint2 xr2 = xb[(size_t)node * xld4 + offR4 + coff];      // xr already fp16
    __half2 xrh[2] = { *reinterpret_cast<__half2*>(&xr2.x), *reinterpret_cast<__half2*>(&xr2.y) };
    const __half2 p2 = __floats2half2_rn(0.2f, 0.2f);

    float ssum = 0.f;
    float acc[4] = {};
    uint2 hv_next = xb[(size_t)g_esrc[beg + h] * xld4 + coff];   // esrc padded -> safe

    for (int j = beg; j < end; j += 2) {
        uint2 hv = hv_next;
        hv_next = xb[(size_t)g_esrc[j + 2 + h] * xld4 + coff];
        const __half2* xvh = reinterpret_cast<const __half2*>(&hv);
        __half2 t0 = __hadd2(xvh[0], xrh[0]);
        __half2 t1 = __hadd2(xvh[1], xrh[1]);
        t0 = __hmax2(t0, __hmul2(t0, p2));           // leaky_relu(0.2)
        t1 = __hmax2(t1, __hmul2(t1, p2));
        __half2 dot = __hmul2(ah[0], t0);
        dot = __hfma2(ah[1], t1, dot);
        float p = __low2float(dot) + __high2float(dot);
        p += __shfl_xor_sync(0xffffffffu, p, 1);
        p += __shfl_xor_sync(0xffffffffu, p, 2);
        p += __shfl_xor_sync(0xffffffffu, p, 4);
        p += __shfl_xor_sync(0xffffffffu, p, 8);
        float w = (j + h < end) ? __expf(p) : 0.f;
        ssum += w;
        float2 x0 = __half22float2(xvh[0]);
        float2 x1 = __half22float2(xvh[1]);
        acc[0] = fmaf(w, x0.x, acc[0]);
        acc[1] = fmaf(w, x0.y, acc[1]);
        acc[2] = fmaf(w, x1.x, acc[2]);
        acc[3] = fmaf(w, x1.y, acc[3]);
    }
    ssum += __shfl_xor_sync(0xffffffffu, ssum, 16);
    #pragma unroll
    for (int k = 0; k < 4; ++k)
        acc[k] += __shfl_xor_sync(0xffffffffu, acc[k], 16);
    if (h != 0) return;

    float inv = 1.f / (ssum + 1e-16f);
    float4 bf4 = *reinterpret_cast<const float4*>(bias + c0);
    float bb[4] = { bf4.x, bf4.y, bf4.z, bf4.w };
    float v[4];
    #pragma unroll
    for (int k = 0; k < 4; ++k) {
        float t = acc[k] * inv + bb[k];
        v[k] = (t > 0.f) ? t : (__expf(t) - 1.f);        // ELU
    }
    if (resf) {
        float4 q = *reinterpret_cast<const float4*>(resf + (size_t)node * ldresf + c0);
        v[0] += q.x; v[1] += q.y; v[2] += q.z; v[3] += q.w;
    } else {
        uint2 rhu = *reinterpret_cast<const uint2*>(resh + (size_t)node * ldresb + c0);
        uint2 rlu = *reinterpret_cast<const uint2*>(resl + (size_t)node * ldresb + c0);
        const __nv_bfloat162* rh2 = reinterpret_cast<const __nv_bfloat162*>(&rhu);
        const __nv_bfloat162* rl2 = reinterpret_cast<const __nv_bfloat162*>(&rlu);
        #pragma unroll
        for (int k = 0; k < 2; ++k) {
            float2 fh = __bfloat1622float2(rh2[k]);
            float2 fl = __bfloat1622float2(rl2[k]);
            v[2 * k]     += fh.x + fl.x;
            v[2 * k + 1] += fh.y + fl.y;
        }
    }
    if (outf)
        *reinterpret_cast<float4*>(outf + (size_t)node * ldoutf + c0) =
            make_float4(v[0], v[1], v[2], v[3]);
    if (outh) {
        __nv_bfloat162 hv2[2], lv2[2];
        #pragma unroll
        for (int k = 0; k < 2; ++k) {
            __nv_bfloat16 b0 = __float2bfloat16(v[2 * k]), b1 = __float2bfloat16(v[2 * k + 1]);
            hv2[k].x = b0; hv2[k].y = b1;
            lv2[k].x = __float2bfloat16(v[2 * k] - __bfloat162float(b0));
            lv2[k].y = __float2bfloat16(v[2 * k + 1] - __bfloat162float(b1));
        }
        *reinterpret_cast<uint2*>(outh + (size_t)node * HCc + c0) = *reinterpret_cast<uint2*>(hv2);
        *reinterpret_cast<uint2*>(outl + (size_t)node * HCc + c0) = *reinterpret_cast<uint2*>(lv2);
    }
    if (outg) {
        __half2 g2[2] = { __floats2half2_rn(v[0], v[1]), __floats2half2_rn(v[2], v[3]) };
        *reinterpret_cast<uint2*>(outg + (size_t)node * HCc + c0) = *reinterpret_cast<uint2*>(g2);
    }
    if (pool_batch) {                              // fused graph pooling (layer 2)
        int g = pool_batch[node];
        #pragma unroll
        for (int k = 0; k < 4; ++k)
            atomicAdd(&g_pool[g * Cc + c0 + k], v[k]);
    }
}

// ---------------- dense head ----------------
__global__ __launch_bounds__(1024) void dense_head(
    const float* __restrict__ d1w, const float* __restrict__ d1b,
    const float* __restrict__ bng, const float* __restrict__ bnb,
    const float* __restrict__ bnm, const float* __restrict__ bnv,
    const float* __restrict__ d2w, const float* __restrict__ d2b,
    float* __restrict__ z)
{
    __shared__ float sp[NGg * Cc];
    __shared__ float t1[NGg * Cc];
    int tid = threadIdx.x;
    for (int idx = tid; idx < NGg * Cc; idx += 1024) sp[idx] = g_pool[idx];
    __syncthreads();
    for (int idx = tid; idx < NGg * Cc; idx += 1024) {
        int r = idx >> 6, c = idx & 63;
        float s = d1b[c];
        #pragma unroll
        for (int k = 0; k < 64; ++k) s = fmaf(sp[r * 64 + k], d1w[k * 64 + c], s);
        s = (s - bnm[c]) * rsqrtf(bnv[c] + 1e-5f) * bng[c] + bnb[c];
        t1[idx] = (s > 0.f) ? s : 0.f;
    }
    __syncthreads();
    for (int idx = tid; idx < NGg * NCc; idx += 1024) {
        int r = idx >> 4, c = idx & 15;
        float s = d2b[c];
        #pragma unroll
        for (int k = 0; k < 64; ++k) s = fmaf(t1[r * 64 + k], d2w[k * 16 + c], s);
        z[idx] = s;
    }
}

// ---------------- host launcher ----------------
extern "C" void kernel_launch(void* const* d_in, const int* in_sizes, int n_in,
                              void* d_out, int out_size)
{
    const float* x      = (const float*)d_in[0];
    const int*   ei     = (const int*)  d_in[1];
    const int*   batch  = (const int*)  d_in[2];
    const float* inp_w  = (const float*)d_in[3];
    const float* inp_b  = (const float*)d_in[4];
    const float* l0_wl  = (const float*)d_in[5];
    const float* l0_bl  = (const float*)d_in[6];
    const float* l0_wr  = (const float*)d_in[7];
    const float* l0_br  = (const float*)d_in[8];
    const float* l0_att = (const float*)d_in[9];
    const float* l0_bias= (const float*)d_in[10];
    const float* l1_wl  = (const float*)d_in[11];
    const float* l1_bl  = (const float*)d_in[12];
    const float* l1_wr  = (const float*)d_in[13];
    const float* l1_br  = (const float*)d_in[14];
    const float* l1_att = (const float*)d_in[15];
    const float* l1_bias= (const float*)d_in[16];
    const float* l2_wl  = (const float*)d_in[17];
    const float* l2_bl  = (const float*)d_in[18];
    const float* l2_wr  = (const float*)d_in[19];
    const float* l2_br  = (const float*)d_in[20];
    const float* l2_att = (const float*)d_in[21];
    const float* l2_bias= (const float*)d_in[22];
    const float* res_w  = (const float*)d_in[23];
    const float* d1_w   = (const float*)d_in[24];
    const float* d1_b   = (const float*)d_in[25];
    const float* bn_g   = (const float*)d_in[26];
    const float* bn_b   = (const float*)d_in[27];
    const float* bn_m   = (const float*)d_in[28];
    const float* bn_v   = (const float*)d_in[29];
    const float* d2_w   = (const float*)d_in[30];
    const float* d2_b   = (const float*)d_in[31];
    float* out = (float*)d_out;

    float *p_big, *p_bias;
    __nv_bfloat16 *p_ah, *p_al, *p_wh, *p_wl;
    __half *p_hf, *p_gh, *p_whf;
    cudaGetSymbolAddress((void**)&p_big,  g_big);
    cudaGetSymbolAddress((void**)&p_ah,   g_ah);
    cudaGetSymbolAddress((void**)&p_al,   g_al);
    cudaGetSymbolAddress((void**)&p_wh,   g_wh);
    cudaGetSymbolAddress((void**)&p_wl,   g_wl);
    cudaGetSymbolAddress((void**)&p_hf,   g_hf);
    cudaGetSymbolAddress((void**)&p_gh,   g_gh);
    cudaGetSymbolAddress((void**)&p_whf,  g_whf);
    cudaGetSymbolAddress((void**)&p_bias, g_biascat);

    cudaFuncSetAttribute(mm_mma,   cudaFuncAttributeMaxDynamicSharedMemorySize, SMEM_MM);
    cudaFuncSetAttribute(mm_mma_h, cudaFuncAttributeMaxDynamicSharedMemorySize, SMEM_MH);

    // fork conv + CSR chain onto side stream (capture-legal fork/join)
    cudaStream_t sB;
    cudaStreamCreateWithFlags(&sB, cudaStreamNonBlocking);
    cudaEvent_t evFork, evConv, evJoin;
    cudaEventCreateWithFlags(&evFork, cudaEventDisableTiming);
    cudaEventCreateWithFlags(&evConv, cudaEventDisableTiming);
    cudaEventCreateWithFlags(&evJoin, cudaEventDisableTiming);

    cudaEventRecord(evFork, 0);
    cudaStreamWaitEvent(sB, evFork, 0);
    conv_hilo<<<(Nn * 128 / 4 + 255) / 256, 256, 0, sB>>>(x, Nn * 128 / 4);
    cudaEventRecord(evConv, sB);
    clearB<<<(Nn + 255) / 256, 256, 0, sB>>>();
    csr_count<<<(EA + 255) / 256, 256, 0, sB>>>(ei);
    csr_scan<<<1, 1024, 0, sB>>>();
    csr_scatter<<<(EA + 255) / 256, 256, 0, sB>>>(ei);
    cudaEventRecord(evJoin, sB);

    // stream A: weight prep (concurrent with conv+CSR)
    prep_all<<<(PREP_TOT + 255) / 256, 256>>>(
        inp_w, l0_wl, l0_wr, l1_wl, l1_wr, l2_wl, l2_wr, res_w,
        inp_b, l0_bl, l0_br, l1_bl, l1_br, l2_bl, l2_br);

    const int MB = 157;  // ceil(20000/128)

    // ---- layer 0: [x_res(fp32,384) | xl | xr (fp16,768)], K=128, 3-term bf16 ----
    cudaStreamWaitEvent(0, evConv, 0);   // ah/al ready
    mm_mma<<<dim3(9, MB), 256, SMEM_MM>>>(p_ah, p_al, p_wh + W0OFF, p_wl + W0OFF,
                                          p_bias + B0OFF, p_big,
                                          p_hf, 768, 384, 768, 128, 384);
    cudaStreamWaitEvent(0, evJoin, 0);   // CSR ready before first gat
    gat_fused<<<Nn, 32 * Hh>>>(p_hf, 192, 96, l0_att, l0_bias,
                               p_big, 384, nullptr, nullptr, 0,
                               nullptr, 0, p_ah, p_al, p_gh, nullptr, Hh, 1);  // h0 -> ah/al + gh

    // ---- layer 1: [xl | xr] fp16, K=384, 1-term fp16 GEMM ----
    mm_mma_h<<<dim3(6, MB), 256, SMEM_MH>>>(p_gh, p_whf, p_bias + B1OFF, p_hf, 384, 768);
    gat_fused<<<Nn, 32 * Hh>>>(p_hf, 192, 96, l1_att, l1_bias,
                               nullptr, 0, p_ah, p_al, HCc,
                               nullptr, 0, p_ah, p_al, nullptr, nullptr, Hh, 1); // res=h0, h1 -> ah/al

    // ---- layer 2: [xl | xr (fp16,128) | res_proj (fp32 at col 128)], K=384, 3-term bf16 ----
    mm_mma<<<dim3(2, MB), 256, SMEM_MM>>>(p_ah, p_al, p_wh + W2OFF, p_wl + W2OFF,
                                          p_bias + B2OFF, p_big - 128,   // fp32 writes at cb>=128 -> col 0
                                          p_hf, 128, 0, 128, 384, 384);
    gat_fused<<<(Nn + 7) / 8, 256>>>(p_hf, 32, 16, l2_att, l2_bias,
                                     p_big, 384, nullptr, nullptr, 0,
                                     out, 64, nullptr, nullptr, nullptr, batch, 1, 8); // h -> d_out, pool

    dense_head<<<1, 1024>>>(d1_w, d1_b, bn_g, bn_b, bn_m, bn_v, d2_w, d2_b,
                            out + (size_t)Nn * Cc);

    cudaEventDestroy(evFork);
    cudaEventDestroy(evConv);
    cudaEventDestroy(evJoin);
    cudaStreamDestroy(sB);
}

// round 16
// speedup vs baseline: 1.3961x; 1.0747x over previous
#include <cuda_runtime.h>
#include <cuda_bf16.h>
#include <cuda_fp16.h>
#include <cstdint>
#include <math.h>

// Problem constants
#define Nn    20000
#define Mpad  20096            // 157 * 128
#define Ee    320000
#define EA    (Ee + Nn)
#define INF_  128
#define Hh    6
#define Cc    64
#define HCc   384
#define NGg   64
#define NCc   16

// weight-prep element offsets in concatenated [N x K] K-major bf16 buffers
#define W0OFF 0                // layer0: 1152 x 128
#define W1OFF 147456           // layer1: 768 x 384
#define W2OFF 442368           // layer2: 256 x 384 (rows 192..255 zero pad)
#define WTOT  540672
#define B0OFF 0
#define B1OFF 1152
#define B2OFF 1920
#define BTOT  2176

// ---------------- device scratch ----------------
__device__ __align__(16) __nv_bfloat16 g_ah[(size_t)Mpad * HCc];
__device__ __align__(16) __nv_bfloat16 g_al[(size_t)Mpad * HCc];
__device__ __align__(16) __half        g_xh[(size_t)Mpad * 128];  // fp16 x (L0 fp16 GEMM A)
__device__ __align__(16) __half        g_hf[(size_t)Mpad * 768];  // fp16 [xl|xr] copy
__device__ __align__(16) __half        g_gh[(size_t)Mpad * HCc];  // fp16 h0 (L1 GEMM A)
__device__ __align__(16) __nv_bfloat16 g_wh[WTOT];
__device__ __align__(16) __nv_bfloat16 g_wl[WTOT];
__device__ __align__(16) __half        g_whf0[768 * 128];         // fp16 W0 (xl|xr rows)
__device__ __align__(16) __half        g_whf[768 * 384];          // fp16 W1
__device__ float g_biascat[BTOT];
__device__ float g_big[(size_t)Mpad * 384];    // fp32 region (x_res / res_proj only)
__device__ int   g_deg[Nn + 1];
__device__ int   g_indptr[Nn + 1];
__device__ int   g_cursor[Nn];
__device__ int   g_esrc[EA + 8];               // src node per CSR slot (+8 pad)
__device__ float g_pool[NGg * Cc];

// ---------------- PTX helpers (plain sm_80+ features only) ----------------
__device__ __forceinline__ uint32_t smem_u32(const void* p) {
    uint32_t a;
    asm("{ .reg .u64 t; cvta.to.shared.u64 t, %1; cvt.u32.u64 %0, t; }" : "=r"(a) : "l"(p));
    return a;
}
#define CPASY16(dst, src) asm volatile("cp.async.cg.shared.global [%0], [%1], 16;" :: "r"(dst), "l"(src))
#define CPASY_COMMIT()    asm volatile("cp.async.commit_group;" ::: "memory")
#define CPASY_WAIT1()     asm volatile("cp.async.wait_group 1;" ::: "memory")
#define CPASY_WAIT0()     asm volatile("cp.async.wait_group 0;" ::: "memory")

__device__ __forceinline__ void ldm_x4(uint32_t* r, uint32_t addr) {
    asm volatile("ldmatrix.sync.aligned.m8n8.x4.shared.b16 {%0,%1,%2,%3}, [%4];"
        : "=r"(r[0]), "=r"(r[1]), "=r"(r[2]), "=r"(r[3]) : "r"(addr));
}
__device__ __forceinline__ void mma_bf16(float* d, const uint32_t* a,
                                         uint32_t b0, uint32_t b1) {
    asm volatile("mma.sync.aligned.m16n8k16.row.col.f32.bf16.bf16.f32 "
        "{%0,%1,%2,%3}, {%4,%5,%6,%7}, {%8,%9}, {%0,%1,%2,%3};"
        : "+f"(d[0]), "+f"(d[1]), "+f"(d[2]), "+f"(d[3])
        : "r"(a[0]), "r"(a[1]), "r"(a[2]), "r"(a[3]), "r"(b0), "r"(b1));
}
__device__ __forceinline__ void mma_fp16(float* d, const uint32_t* a,
                                         uint32_t b0, uint32_t b1) {
    asm volatile("mma.sync.aligned.m16n8k16.row.col.f32.f16.f16.f32 "
        "{%0,%1,%2,%3}, {%4,%5,%6,%7}, {%8,%9}, {%0,%1,%2,%3};"
        : "+f"(d[0]), "+f"(d[1]), "+f"(d[2]), "+f"(d[3])
        : "r"(a[0]), "r"(a[1]), "r"(a[2]), "r"(a[3]), "r"(b0), "r"(b1));
}

// ---------------- prep: weight split + bias concat (stream A) ----------------
__global__ void prep_all(
    const float* __restrict__ inpw,
    const float* __restrict__ l0wl, const float* __restrict__ l0wr,
    const float* __restrict__ l1wl, const float* __restrict__ l1wr,
    const float* __restrict__ l2wl, const float* __restrict__ l2wr,
    const float* __restrict__ resw,
    const float* __restrict__ inpb,
    const float* __restrict__ l0bl, const float* __restrict__ l0br,
    const float* __restrict__ l1bl, const float* __restrict__ l1br,
    const float* __restrict__ l2bl, const float* __restrict__ l2br)
{
    int idx = blockIdx.x * blockDim.x + threadIdx.x;
    if (idx < WTOT) {
        float v;
        if (idx < W1OFF) {                       // W0: 1152 x 128 (xl|xr also fp16)
            int ng = idx >> 7, k = idx & 127;
            int sub = ng / 384, nl = ng - sub * 384;
            const float* w = (sub == 0) ? inpw : (sub == 1) ? l0wl : l0wr;
            v = w[k * 384 + nl];
            if (ng >= 384) g_whf0[idx - 384 * 128] = __float2half(v);
        } else if (idx < W2OFF) {                // W1: 768 x 384 (also fp16 copy)
            int rem = idx - W1OFF;
            int ng = rem / 384, k = rem - ng * 384;
            const float* w = (ng < 384) ? l1wl : l1wr;
            int nl = (ng < 384) ? ng : ng - 384;
            v = w[k * 384 + nl];
            g_whf[rem] = __float2half(v);
        } else {                                 // W2: 256 x 384 (pad >=192)
            int rem = idx - W2OFF;
            int ng = rem / 384, k = rem - ng * 384;
            if      (ng < 64)  v = l2wl[k * 64 + ng];
            else if (ng < 128) v = l2wr[k * 64 + ng - 64];
            else if (ng < 192) v = resw[k * 64 + ng - 128];
            else               v = 0.f;
        }
        __nv_bfloat16 hi = __float2bfloat16(v);
        g_wh[idx] = hi;
        g_wl[idx] = __float2bfloat16(v - __bfloat162float(hi));
        return;
    }
    int r = idx - WTOT;
    if (r < BTOT) {
        float v = 0.f;
        if      (r < 384)  v = inpb[r];
        else if (r < 768)  v = l0bl[r - 384];
        else if (r < 1152) v = l0br[r - 768];
        else if (r < 1536) v = l1bl[r - 1152];
        else if (r < 1920) v = l1br[r - 1536];
        else if (r < 1984) v = l2bl[r - 1920];
        else if (r < 2048) v = l2br[r - 1984];
        g_biascat[r] = v;
    }
}
#define PREP_TOT (WTOT + BTOT)

// ---------------- CSR build + clears (stream B) ----------------
__global__ void clearB() {     // deg + pool + esrc pad
    int i = blockIdx.x * blockDim.x + threadIdx.x;
    if (i < Nn) g_deg[i] = 0;
    if (i < NGg * Cc) g_pool[i] = 0.f;
    if (i < 8) g_esrc[EA + i] = 0;
}

__global__ void csr_count(const int* __restrict__ ei) {
    int e = blockIdx.x * blockDim.x + threadIdx.x;
    if (e >= EA) return;
    int d = (e < Ee) ? ei[Ee + e] : (e - Ee);
    atomicAdd(&g_deg[d], 1);
}

__global__ void csr_scan() {
    __shared__ int part[1024];
    const int per = (Nn + 1023) / 1024;
    int t = threadIdx.x;
    int s = 0;
    #pragma unroll
    for (int k = 0; k < per; ++k) { int i = t * per + k; if (i < Nn) s += g_deg[i]; }
    part[t] = s;
    __syncthreads();
    for (int off = 1; off < 1024; off <<= 1) {
        int v = (t >= off) ? part[t - off] : 0;
        __syncthreads();
        part[t] += v;
        __syncthreads();
    }
    int run = part[t] - s;
    #pragma unroll
    for (int k = 0; k < per; ++k) {
        int i = t * per + k;
        if (i < Nn) { g_indptr[i] = run; g_cursor[i] = run; run += g_deg[i]; }
    }
    if (t == 0) g_indptr[Nn] = EA;
}

__global__ void csr_scatter(const int* __restrict__ ei) {
    int e = blockIdx.x * blockDim.x + threadIdx.x;
    if (e >= EA) return;
    int s, d;
    if (e < Ee) { s = ei[e]; d = ei[Ee + e]; }
    else        { s = d = e - Ee; }
    int pos = atomicAdd(&g_cursor[d], 1);
    g_esrc[pos] = s;
}

// fp32 -> bf16 hi/lo + fp16 copy of x (stream B)
__global__ void conv_hilo(const float* __restrict__ src, int n4) {
    int i = blockIdx.x * blockDim.x + threadIdx.x;
    if (i >= n4) return;
    float4 v = reinterpret_cast<const float4*>(src)[i];
    __nv_bfloat16 h0 = __float2bfloat16(v.x), h1 = __float2bfloat16(v.y);
    __nv_bfloat16 h2 = __float2bfloat16(v.z), h3 = __float2bfloat16(v.w);
    g_ah[i * 4 + 0] = h0; g_ah[i * 4 + 1] = h1;
    g_ah[i * 4 + 2] = h2; g_ah[i * 4 + 3] = h3;
    g_al[i * 4 + 0] = __float2bfloat16(v.x - __bfloat162float(h0));
    g_al[i * 4 + 1] = __float2bfloat16(v.y - __bfloat162float(h1));
    g_al[i * 4 + 2] = __float2bfloat16(v.z - __bfloat162float(h2));
    g_al[i * 4 + 3] = __float2bfloat16(v.w - __bfloat162float(h3));
    reinterpret_cast<__half2*>(g_xh)[i * 2]     = __floats2half2_rn(v.x, v.y);
    reinterpret_cast<__half2*>(g_xh)[i * 2 + 1] = __floats2half2_rn(v.z, v.w);
}

// ---------------- HMMA split-bf16 GEMM, 4-buffer single-K-pass ----------------
#define PADK 40
#define TILEB (128 * PADK * 2)     // 10240 bytes per tile
#define STAGEB (4 * TILEB)         // 40960 bytes per stage
#define SMEM_MM (2 * STAGEB)       // 81920
#define STAGEB_H (2 * TILEB)       // 20480
#define SMEM_MH (2 * STAGEB_H)     // 40960

__global__ __launch_bounds__(256, 2) void mm_mma(
    const __nv_bfloat16* __restrict__ Ah, const __nv_bfloat16* __restrict__ Al,
    const __nv_bfloat16* __restrict__ Bh, const __nv_bfloat16* __restrict__ Bl,
    const float* __restrict__ bias, float* __restrict__ out,
    __half* __restrict__ hout, int hld, int hcol0, int hcolw,
    int K, int ldout)
{
    extern __shared__ __align__(16) char dsm[];
    uint32_t sbase = smem_u32(dsm);
    int tid = threadIdx.x, wid = tid >> 5, lane = tid & 31;
    int m0 = blockIdx.y * 128, n0 = blockIdx.x * 128;
    int warp_m = wid & 3, warp_n = wid >> 2;
    int nk = K >> 5;

    auto load_chunk = [&](int stage, int k0) {
        uint32_t dst0 = sbase + stage * STAGEB;
        #pragma unroll
        for (int it = 0; it < 8; ++it) {
            int idx = tid + it * 256;
            int buf = idx >> 9;
            int w   = idx & 511;
            int r   = w >> 2, q = w & 3;
            const __nv_bfloat16* src;
            if      (buf == 0) src = Ah + (size_t)(m0 + r) * K + k0 + q * 8;
            else if (buf == 1) src = Al + (size_t)(m0 + r) * K + k0 + q * 8;
            else if (buf == 2) src = Bh + (size_t)(n0 + r) * K + k0 + q * 8;
            else               src = Bl + (size_t)(n0 + r) * K + k0 + q * 8;
            CPASY16(dst0 + buf * TILEB + (r * PADK + q * 8) * 2, src);
        }
        CPASY_COMMIT();
    };

    load_chunk(0, 0);

    float acc[2][8][4];
    #pragma unroll
    for (int mi = 0; mi < 2; ++mi)
        #pragma unroll
        for (int nt = 0; nt < 8; ++nt)
            #pragma unroll
            for (int q = 0; q < 4; ++q) acc[mi][nt][q] = 0.f;

    int gA = lane >> 3, lrA = lane & 7;

    for (int c = 0; c < nk; ++c) {
        int s = c & 1;
        if (c + 1 < nk) { load_chunk(s ^ 1, (c + 1) << 5); CPASY_WAIT1(); }
        else            { CPASY_WAIT0(); }
        __syncthreads();

        uint32_t st = sbase + s * STAGEB;
        uint32_t aH = st + (warp_m * 32) * PADK * 2;
        uint32_t aL = st + TILEB + (warp_m * 32) * PADK * 2;
        uint32_t bH = st + 2 * TILEB + (warp_n * 64) * PADK * 2;
        uint32_t bL = st + 3 * TILEB + (warp_n * 64) * PADK * 2;

        #pragma unroll
        for (int kk = 0; kk < 32; kk += 16) {
            uint32_t afrH[2][4], afrL[2][4];
            #pragma unroll
            for (int mi = 0; mi < 2; ++mi) {
                int row = mi * 16 + ((gA & 1) << 3) + lrA;
                int col = ((gA >> 1) << 3) + kk;
                ldm_x4(afrH[mi], aH + (row * PADK + col) * 2);
                ldm_x4(afrL[mi], aL + (row * PADK + col) * 2);
            }
            uint32_t bfr[4][4];
            #pragma unroll
            for (int nb = 0; nb < 4; ++nb) {
                int n = nb * 16 + ((gA >> 1) << 3) + lrA;
                int col = ((gA & 1) << 3) + kk;
                ldm_x4(bfr[nb], bH + (n * PADK + col) * 2);
            }
            #pragma unroll
            for (int mi = 0; mi < 2; ++mi)
                #pragma unroll
                for (int nt = 0; nt < 8; ++nt) {
                    mma_bf16(acc[mi][nt], afrH[mi],
                             bfr[nt >> 1][(nt & 1) * 2], bfr[nt >> 1][(nt & 1) * 2 + 1]);
                    mma_bf16(acc[mi][nt], afrL[mi],
                             bfr[nt >> 1][(nt & 1) * 2], bfr[nt >> 1][(nt & 1) * 2 + 1]);
                }
            #pragma unroll
            for (int nb = 0; nb < 4; ++nb) {
                int n = nb * 16 + ((gA >> 1) << 3) + lrA;
                int col = ((gA & 1) << 3) + kk;
                ldm_x4(bfr[nb], bL + (n * PADK + col) * 2);
            }
            #pragma unroll
            for (int mi = 0; mi < 2; ++mi)
                #pragma unroll
                for (int nt = 0; nt < 8; ++nt)
                    mma_bf16(acc[mi][nt], afrH[mi],
                             bfr[nt >> 1][(nt & 1) * 2], bfr[nt >> 1][(nt & 1) * 2 + 1]);
        }
        __syncthreads();
    }

    int rl = lane >> 2, cl = (lane & 3) * 2;
    #pragma unroll
    for (int mi = 0; mi < 2; ++mi) {
        int r0 = m0 + warp_m * 32 + mi * 16 + rl;
        #pragma unroll
        for (int nt = 0; nt < 8; ++nt) {
            int cb = n0 + warp_n * 64 + nt * 8 + cl;
            float b0 = bias[cb], b1 = bias[cb + 1];
            bool inh = (unsigned)(cb - hcol0) < (unsigned)hcolw;
            int hc = cb - hcol0;
            if (r0 < Nn) {
                float v0 = acc[mi][nt][0] + b0, v1 = acc[mi][nt][1] + b1;
                if (inh)
                    *reinterpret_cast<__half2*>(&hout[(size_t)r0 * hld + hc]) = __floats2half2_rn(v0, v1);
                else {
                    float2 v = { v0, v1 };
                    *reinterpret_cast<float2*>(&out[(size_t)r0 * ldout + cb]) = v;
                }
            }
            if (r0 + 8 < Nn) {
                float v0 = acc[mi][nt][2] + b0, v1 = acc[mi][nt][3] + b1;
                if (inh)
                    *reinterpret_cast<__half2*>(&hout[(size_t)(r0 + 8) * hld + hc]) = __floats2half2_rn(v0, v1);
                else {
                    float2 v = { v0, v1 };
                    *reinterpret_cast<float2*>(&out[(size_t)(r0 + 8) * ldout + cb]) = v;
                }
            }
        }
    }
}

// ---------------- HMMA fp16 1-term GEMM, 2-buffer ----------------
__global__ __launch_bounds__(256, 2) void mm_mma_h(
    const __half* __restrict__ A, const __half* __restrict__ B,
    const float* __restrict__ bias, __half* __restrict__ out,
    int K, int ldout)
{
    extern __shared__ __align__(16) char dsm[];
    uint32_t sbase = smem_u32(dsm);
    int tid = threadIdx.x, wid = tid >> 5, lane = tid & 31;
    int m0 = blockIdx.y * 128, n0 = blockIdx.x * 128;
    int warp_m = wid & 3, warp_n = wid >> 2;
    int nk = K >> 5;

    auto load_chunk = [&](int stage, int k0) {
        uint32_t dst0 = sbase + stage * STAGEB_H;
        #pragma unroll
        for (int it = 0; it < 4; ++it) {
            int idx = tid + it * 256;       // 0..1023
            int buf = idx >> 9;             // 0=A, 1=B
            int w   = idx & 511;
            int r   = w >> 2, q = w & 3;
            const __half* src = (buf == 0)
                ? A + (size_t)(m0 + r) * K + k0 + q * 8
                : B + (size_t)(n0 + r) * K + k0 + q * 8;
            CPASY16(dst0 + buf * TILEB + (r * PADK + q * 8) * 2, src);
        }
        CPASY_COMMIT();
    };

    load_chunk(0, 0);

    float acc[2][8][4];
    #pragma unroll
    for (int mi = 0; mi < 2; ++mi)
        #pragma unroll
        for (int nt = 0; nt < 8; ++nt)
            #pragma unroll
            for (int q = 0; q < 4; ++q) acc[mi][nt][q] = 0.f;

    int gA = lane >> 3, lrA = lane & 7;

    for (int c = 0; c < nk; ++c) {
        int s = c & 1;
        if (c + 1 < nk) { load_chunk(s ^ 1, (c + 1) << 5); CPASY_WAIT1(); }
        else            { CPASY_WAIT0(); }
        __syncthreads();

        uint32_t st = sbase + s * STAGEB_H;
        uint32_t aT = st + (warp_m * 32) * PADK * 2;
        uint32_t bT = st + TILEB + (warp_n * 64) * PADK * 2;

        #pragma unroll
        for (int kk = 0; kk < 32; kk += 16) {
            uint32_t afr[2][4];
            #pragma unroll
            for (int mi = 0; mi < 2; ++mi) {
                int row = mi * 16 + ((gA & 1) << 3) + lrA;
                int col = ((gA >> 1) << 3) + kk;
                ldm_x4(afr[mi], aT + (row * PADK + col) * 2);
            }
            uint32_t bfr[4][4];
            #pragma unroll
            for (int nb = 0; nb < 4; ++nb) {
                int n = nb * 16 + ((gA >> 1) << 3) + lrA;
                int col = ((gA & 1) << 3) + kk;
                ldm_x4(bfr[nb], bT + (n * PADK + col) * 2);
            }
            #pragma unroll
            for (int mi = 0; mi < 2; ++mi)
                #pragma unroll
                for (int nt = 0; nt < 8; ++nt)
                    mma_fp16(acc[mi][nt], afr[mi],
                             bfr[nt >> 1][(nt & 1) * 2], bfr[nt >> 1][(nt & 1) * 2 + 1]);
        }
        __syncthreads();
    }

    int rl = lane >> 2, cl = (lane & 3) * 2;
    #pragma unroll
    for (int mi = 0; mi < 2; ++mi) {
        int r0 = m0 + warp_m * 32 + mi * 16 + rl;
        #pragma unroll
        for (int nt = 0; nt < 8; ++nt) {
            int cb = n0 + warp_n * 64 + nt * 8 + cl;
            float b0 = bias[cb], b1 = bias[cb + 1];
            if (r0 < Nn)
                *reinterpret_cast<__half2*>(&out[(size_t)r0 * ldout + cb]) =
                    __floats2half2_rn(acc[mi][nt][0] + b0, acc[mi][nt][1] + b1);
            if (r0 + 8 < Nn)
                *reinterpret_cast<__half2*>(&out[(size_t)(r0 + 8) * ldout + cb]) =
                    __floats2half2_rn(acc[mi][nt][2] + b0, acc[mi][nt][3] + b1);
        }
    }
}

// ---------------- fused GATv2: convergent 2-edge half-warp, all-fp16 inputs ----------------
__global__ void gat_fused(
    const __half* __restrict__ xh, int xld4, int offR4,
    const float* __restrict__ att, const float* __restrict__ bias,
    const float* __restrict__ resf, int ldresf,
    const __nv_bfloat16* __restrict__ resh, const __nv_bfloat16* __restrict__ resl, int ldresb,
    float* __restrict__ outf, int ldoutf,
    __nv_bfloat16* __restrict__ outh, __nv_bfloat16* __restrict__ outl,
    __half* __restrict__ outg,
    const int* __restrict__ pool_batch, int H, int npb)
{
    int wid = threadIdx.x >> 5;
    int lane = threadIdx.x & 31;
    int node = blockIdx.x * npb + wid / H;
    int head = wid - (wid / H) * H;
    if (node >= Nn) return;
    int h = lane >> 4, gl = lane & 15;
    int beg = g_indptr[node], end = g_indptr[node + 1];
    int c0 = head * 64 + gl * 4;
    int coff = head * 16 + gl;

    const uint2* xb = reinterpret_cast<const uint2*>(xh);
    float4 af = *reinterpret_cast<const float4*>(att + c0);
    __half2 ah[2] = { __floats2half2_rn(af.x, af.y), __floats2half2_rn(af.z, af.w) };
    uint2 xr2 = xb[(size_t)node * xld4 + offR4 + coff];      // xr already fp16
    __half2 xrh[2] = { *reinterpret_cast<__half2*>(&xr2.x), *reinterpret_cast<__half2*>(&xr2.y) };
    const __half2 p2 = __floats2half2_rn(0.2f, 0.2f);

    float ssum = 0.f;
    float acc[4] = {};
    uint2 hv_next = xb[(size_t)g_esrc[beg + h] * xld4 + coff];   // esrc padded -> safe

    for (int j = beg; j < end; j += 2) {
        uint2 hv = hv_next;
        hv_next = xb[(size_t)g_esrc[j + 2 + h] * xld4 + coff];
        const __half2* xvh = reinterpret_cast<const __half2*>(&hv);
        __half2 t0 = __hadd2(xvh[0], xrh[0]);
        __half2 t1 = __hadd2(xvh[1], xrh[1]);
        t0 = __hmax2(t0, __hmul2(t0, p2));           // leaky_relu(0.2)
        t1 = __hmax2(t1, __hmul2(t1, p2));
        __half2 dot = __hmul2(ah[0], t0);
        dot = __hfma2(ah[1], t1, dot);
        float p = __low2float(dot) + __high2float(dot);
        p += __shfl_xor_sync(0xffffffffu, p, 1);
        p += __shfl_xor_sync(0xffffffffu, p, 2);
        p += __shfl_xor_sync(0xffffffffu, p, 4);
        p += __shfl_xor_sync(0xffffffffu, p, 8);
        float w = (j + h < end) ? __expf(p) : 0.f;
        ssum += w;
        float2 x0 = __half22float2(xvh[0]);
        float2 x1 = __half22float2(xvh[1]);
        acc[0] = fmaf(w, x0.x, acc[0]);
        acc[1] = fmaf(w, x0.y, acc[1]);
        acc[2] = fmaf(w, x1.x, acc[2]);
        acc[3] = fmaf(w, x1.y, acc[3]);
    }
    ssum += __shfl_xor_sync(0xffffffffu, ssum, 16);
    #pragma unroll
    for (int k = 0; k < 4; ++k)
        acc[k] += __shfl_xor_sync(0xffffffffu, acc[k], 16);
    if (h != 0) return;

    float inv = 1.f / (ssum + 1e-16f);
    float4 bf4 = *reinterpret_cast<const float4*>(bias + c0);
    float bb[4] = { bf4.x, bf4.y, bf4.z, bf4.w };
    float v[4];
    #pragma unroll
    for (int k = 0; k < 4; ++k) {
        float t = acc[k] * inv + bb[k];
        v[k] = (t > 0.f) ? t : (__expf(t) - 1.f);        // ELU
    }
    if (resf) {
        float4 q = *reinterpret_cast<const float4*>(resf + (size_t)node * ldresf + c0);
        v[0] += q.x; v[1] += q.y; v[2] += q.z; v[3] += q.w;
    } else {
        uint2 rhu = *reinterpret_cast<const uint2*>(resh + (size_t)node * ldresb + c0);
        uint2 rlu = *reinterpret_cast<const uint2*>(resl + (size_t)node * ldresb + c0);
        const __nv_bfloat162* rh2 = reinterpret_cast<const __nv_bfloat162*>(&rhu);
        const __nv_bfloat162* rl2 = reinterpret_cast<const __nv_bfloat162*>(&rlu);
        #pragma unroll
        for (int k = 0; k < 2; ++k) {
            float2 fh = __bfloat1622float2(rh2[k]);
            float2 fl = __bfloat1622float2(rl2[k]);
            v[2 * k]     += fh.x + fl.x;
            v[2 * k + 1] += fh.y + fl.y;
        }
    }
    if (outf)
        *reinterpret_cast<float4*>(outf + (size_t)node * ldoutf + c0) =
            make_float4(v[0], v[1], v[2], v[3]);
    if (outh) {
        __nv_bfloat162 hv2[2], lv2[2];
        #pragma unroll
        for (int k = 0; k < 2; ++k) {
            __nv_bfloat16 b0 = __float2bfloat16(v[2 * k]), b1 = __float2bfloat16(v[2 * k + 1]);
            hv2[k].x = b0; hv2[k].y = b1;
            lv2[k].x = __float2bfloat16(v[2 * k] - __bfloat162float(b0));
            lv2[k].y = __float2bfloat16(v[2 * k + 1] - __bfloat162float(b1));
        }
        *reinterpret_cast<uint2*>(outh + (size_t)node * HCc + c0) = *reinterpret_cast<uint2*>(hv2);
        *reinterpret_cast<uint2*>(outl + (size_t)node * HCc + c0) = *reinterpret_cast<uint2*>(lv2);
    }
    if (outg) {
        __half2 g2[2] = { __floats2half2_rn(v[0], v[1]), __floats2half2_rn(v[2], v[3]) };
        *reinterpret_cast<uint2*>(outg + (size_t)node * HCc + c0) = *reinterpret_cast<uint2*>(g2);
    }
    if (pool_batch) {                              // fused graph pooling (layer 2)
        int g = pool_batch[node];
        #pragma unroll
        for (int k = 0; k < 4; ++k)
            atomicAdd(&g_pool[g * Cc + c0 + k], v[k]);
    }
}

// ---------------- dense head ----------------
__global__ __launch_bounds__(1024) void dense_head(
    const float* __restrict__ d1w, const float* __restrict__ d1b,
    const float* __restrict__ bng, const float* __restrict__ bnb,
    const float* __restrict__ bnm, const float* __restrict__ bnv,
    const float* __restrict__ d2w, const float* __restrict__ d2b,
    float* __restrict__ z)
{
    __shared__ float sp[NGg * Cc];
    __shared__ float t1[NGg * Cc];
    int tid = threadIdx.x;
    for (int idx = tid; idx < NGg * Cc; idx += 1024) sp[idx] = g_pool[idx];
    __syncthreads();
    for (int idx = tid; idx < NGg * Cc; idx += 1024) {
        int r = idx >> 6, c = idx & 63;
        float s = d1b[c];
        #pragma unroll
        for (int k = 0; k < 64; ++k) s = fmaf(sp[r * 64 + k], d1w[k * 64 + c], s);
        s = (s - bnm[c]) * rsqrtf(bnv[c] + 1e-5f) * bng[c] + bnb[c];
        t1[idx] = (s > 0.f) ? s : 0.f;
    }
    __syncthreads();
    for (int idx = tid; idx < NGg * NCc; idx += 1024) {
        int r = idx >> 4, c = idx & 15;
        float s = d2b[c];
        #pragma unroll
        for (int k = 0; k < 64; ++k) s = fmaf(t1[r * 64 + k], d2w[k * 16 + c], s);
        z[idx] = s;
    }
}

// ---------------- host launcher ----------------
extern "C" void kernel_launch(void* const* d_in, const int* in_sizes, int n_in,
                              void* d_out, int out_size)
{
    const float* x      = (const float*)d_in[0];
    const int*   ei     = (const int*)  d_in[1];
    const int*   batch  = (const int*)  d_in[2];
    const float* inp_w  = (const float*)d_in[3];
    const float* inp_b  = (const float*)d_in[4];
    const float* l0_wl  = (const float*)d_in[5];
    const float* l0_bl  = (const float*)d_in[6];
    const float* l0_wr  = (const float*)d_in[7];
    const float* l0_br  = (const float*)d_in[8];
    const float* l0_att = (const float*)d_in[9];
    const float* l0_bias= (const float*)d_in[10];
    const float* l1_wl  = (const float*)d_in[11];
    const float* l1_bl  = (const float*)d_in[12];
    const float* l1_wr  = (const float*)d_in[13];
    const float* l1_br  = (const float*)d_in[14];
    const float* l1_att = (const float*)d_in[15];
    const float* l1_bias= (const float*)d_in[16];
    const float* l2_wl  = (const float*)d_in[17];
    const float* l2_bl  = (const float*)d_in[18];
    const float* l2_wr  = (const float*)d_in[19];
    const float* l2_br  = (const float*)d_in[20];
    const float* l2_att = (const float*)d_in[21];
    const float* l2_bias= (const float*)d_in[22];
    const float* res_w  = (const float*)d_in[23];
    const float* d1_w   = (const float*)d_in[24];
    const float* d1_b   = (const float*)d_in[25];
    const float* bn_g   = (const float*)d_in[26];
    const float* bn_b   = (const float*)d_in[27];
    const float* bn_m   = (const float*)d_in[28];
    const float* bn_v   = (const float*)d_in[29];
    const float* d2_w   = (const float*)d_in[30];
    const float* d2_b   = (const float*)d_in[31];
    float* out = (float*)d_out;

    float *p_big, *p_bias;
    __nv_bfloat16 *p_ah, *p_al, *p_wh, *p_wl;
    __half *p_xh, *p_hf, *p_gh, *p_whf0, *p_whf;
    cudaGetSymbolAddress((void**)&p_big,  g_big);
    cudaGetSymbolAddress((void**)&p_ah,   g_ah);
    cudaGetSymbolAddress((void**)&p_al,   g_al);
    cudaGetSymbolAddress((void**)&p_wh,   g_wh);
    cudaGetSymbolAddress((void**)&p_wl,   g_wl);
    cudaGetSymbolAddress((void**)&p_xh,   g_xh);
    cudaGetSymbolAddress((void**)&p_hf,   g_hf);
    cudaGetSymbolAddress((void**)&p_gh,   g_gh);
    cudaGetSymbolAddress((void**)&p_whf0, g_whf0);
    cudaGetSymbolAddress((void**)&p_whf,  g_whf);
    cudaGetSymbolAddress((void**)&p_bias, g_biascat);

    cudaFuncSetAttribute(mm_mma,   cudaFuncAttributeMaxDynamicSharedMemorySize, SMEM_MM);
    cudaFuncSetAttribute(mm_mma_h, cudaFuncAttributeMaxDynamicSharedMemorySize, SMEM_MH);

    // fork conv + CSR chain onto side stream (capture-legal fork/join)
    cudaStream_t sB;
    cudaStreamCreateWithFlags(&sB, cudaStreamNonBlocking);
    cudaEvent_t evFork, evConv, evJoin;
    cudaEventCreateWithFlags(&evFork, cudaEventDisableTiming);
    cudaEventCreateWithFlags(&evConv, cudaEventDisableTiming);
    cudaEventCreateWithFlags(&evJoin, cudaEventDisableTiming);

    cudaEventRecord(evFork, 0);
    cudaStreamWaitEvent(sB, evFork, 0);
    conv_hilo<<<(Nn * 128 / 4 + 255) / 256, 256, 0, sB>>>(x, Nn * 128 / 4);
    cudaEventRecord(evConv, sB);
    clearB<<<(Nn + 255) / 256, 256, 0, sB>>>();
    csr_count<<<(EA + 255) / 256, 256, 0, sB>>>(ei);
    csr_scan<<<1, 1024, 0, sB>>>();
    csr_scatter<<<(EA + 255) / 256, 256, 0, sB>>>(ei);
    cudaEventRecord(evJoin, sB);

    // stream A: weight prep (concurrent with conv+CSR)
    prep_all<<<(PREP_TOT + 255) / 256, 256>>>(
        inp_w, l0_wl, l0_wr, l1_wl, l1_wr, l2_wl, l2_wr, res_w,
        inp_b, l0_bl, l0_br, l1_bl, l1_br, l2_bl, l2_br);

    const int MB = 157;  // ceil(20000/128)

    // ---- layer 0 (split): x_res via 3-term bf16 (N=384, fp32 out);
    //                       xl|xr via 1-term fp16 (N=768, fp16 out) ----
    cudaStreamWaitEvent(0, evConv, 0);   // ah/al/xh ready
    mm_mma<<<dim3(3, MB), 256, SMEM_MM>>>(p_ah, p_al, p_wh + W0OFF, p_wl + W0OFF,
                                          p_bias + B0OFF, p_big,
                                          p_hf, 768, 1152, 0, 128, 384);   // no fp16 window
    mm_mma_h<<<dim3(6, MB), 256, SMEM_MH>>>(p_xh, p_whf0, p_bias + B0OFF + 384, p_hf, 128, 768);
    cudaStreamWaitEvent(0, evJoin, 0);   // CSR ready before first gat
    gat_fused<<<Nn, 32 * Hh>>>(p_hf, 192, 96, l0_att, l0_bias,
                               p_big, 384, nullptr, nullptr, 0,
                               nullptr, 0, p_ah, p_al, p_gh, nullptr, Hh, 1);  // h0 -> ah/al + gh

    // ---- layer 1: [xl | xr] fp16, K=384, 1-term fp16 GEMM ----
    mm_mma_h<<<dim3(6, MB), 256, SMEM_MH>>>(p_gh, p_whf, p_bias + B1OFF, p_hf, 384, 768);
    gat_fused<<<Nn, 32 * Hh>>>(p_hf, 192, 96, l1_att, l1_bias,
                               nullptr, 0, p_ah, p_al, HCc,
                               nullptr, 0, p_ah, p_al, nullptr, nullptr, Hh, 1); // res=h0, h1 -> ah/al

    // ---- layer 2: [xl | xr (fp16,128) | res_proj (fp32 at col 128)], K=384, 3-term bf16 ----
    mm_mma<<<dim3(2, MB), 256, SMEM_MM>>>(p_ah, p_al, p_wh + W2OFF, p_wl + W2OFF,
                                          p_bias + B2OFF, p_big - 128,   // fp32 writes at cb>=128 -> col 0
                                          p_hf, 128, 0, 128, 384, 384);
    gat_fused<<<(Nn + 7) / 8, 256>>>(p_hf, 32, 16, l2_att, l2_bias,
                                     p_big, 384, nullptr, nullptr, 0,
                                     out, 64, nullptr, nullptr, nullptr, batch, 1, 8); // h -> d_out, pool

    dense_head<<<1, 1024>>>(d1_w, d1_b, bn_g, bn_b, bn_m, bn_v, d2_w, d2_b,
                            out + (size_t)Nn * Cc);

    cudaEventDestroy(evFork);
    cudaEventDestroy(evConv);
    cudaEventDestroy(evJoin);
    cudaStreamDestroy(sB);
}